// round 12
// baseline (speedup 1.0000x reference)
#include <cuda_runtime.h>
#include <cstdint>
#include <math.h>

#define Bv 2
#define Sv 2048
#define Dv 2048
#define Hv 16
#define DHv 128
#define FFv 8192
#define M_TOT (Bv*Sv)            // 4096
#define N_FUSED (3*Dv + FFv)     // 14336
#define EPSv 1e-6f

#if defined(__CUDA_ARCH__) && (defined(__CUDA_ARCH_FEAT_SM103_ALL) || defined(__CUDA_ARCH_SPECIFIC__))
#define HAS_TCGEN05 1
#else
#define HAS_TCGEN05 0
#endif

// ---------------- scratch (static device globals; no allocations) --------
__device__ float g_fused[58720256];   // 4096 x 14336
__device__ float g_o[8388608];        // 4096 x 2048   (tf32-rounded)
__device__ float g_attn[8388608];     // 4096 x 2048
__device__ float g_h[33554432];       // 4096 x 8192   (tf32-rounded)
__device__ float g_ffo[8388608];      // 4096 x 2048   (attn + silu(ff))
__device__ float g_xr[8388608];       // 4096 x 2048   rounded x
__device__ float g_wfT[29360128];     // 14336 x 2048  W_fused^T rounded
__device__ float g_waT[4194304];      // 2048 x 2048   W_attn^T rounded
__device__ float g_ffT[16777216];     // 2048 x 8192   W_ff^T rounded

// ================= helpers ================================================
__device__ __forceinline__ uint32_t smem_u32(const void* p) {
    uint32_t a;
    asm("{ .reg .u64 t; cvta.to.shared.u64 t, %1; cvt.u32.u64 %0, t; }"
        : "=r"(a) : "l"(p));
    return a;
}
__device__ __forceinline__ uint32_t f2tf32(float x) {
    return (__float_as_uint(x) + 0x1000u) & 0xFFFFE000u;
}
__device__ __forceinline__ float roundtf(float x) {
    return __uint_as_float(f2tf32(x));
}

#if HAS_TCGEN05
__device__ __forceinline__ uint32_t elect_one() {
    uint32_t pred;
    asm volatile("{\n\t.reg .pred p;\n\telect.sync _|p, 0xFFFFFFFF;\n\t"
                 "selp.b32 %0, 1, 0, p;\n\t}" : "=r"(pred));
    return pred;
}
__device__ __forceinline__ void mbar_init(uint32_t a, uint32_t cnt) {
    asm volatile("mbarrier.init.shared.b64 [%0], %1;" :: "r"(a), "r"(cnt) : "memory");
}
__device__ __forceinline__ void mbar_wait(uint32_t a, uint32_t parity) {
    asm volatile(
        "{\n\t.reg .pred P;\n\t"
        "W%=:\n\t"
        "mbarrier.try_wait.parity.acquire.cta.shared::cta.b64 P, [%0], %1, 0x989680;\n\t"
        "@!P bra W%=;\n\t}"
        :: "r"(a), "r"(parity) : "memory");
}
__device__ __forceinline__ uint64_t make_desc_sw128(uint32_t addr) {
    const uint64_t base =
        (uint64_t(2)  << 61) | (uint64_t(1) << 46) |
        (uint64_t(64) << 32) | (uint64_t(1) << 16);
    return base | ((uint64_t)(addr >> 4) & 0x3FFF);
}
__device__ __forceinline__ void mma_tf32(uint32_t d, uint64_t ad, uint64_t bd,
                                         uint32_t idesc, uint32_t en) {
    asm volatile(
        "{\n\t.reg .pred p;\n\t"
        "setp.ne.u32 p, %4, 0;\n\t"
        "tcgen05.mma.cta_group::1.kind::tf32 [%0], %1, %2, %3, {%5, %5, %5, %5}, p;\n\t}"
        :: "r"(d), "l"(ad), "l"(bd), "r"(idesc), "r"(en), "r"(0u) : "memory");
}
__device__ __forceinline__ void cpasync16(uint32_t dst, const void* src) {
    asm volatile("cp.async.cg.shared.global [%0], [%1], 16;"
                 :: "r"(dst), "l"(src) : "memory");
}
// all prior cp.async of THIS thread arrive on mbarrier at completion
__device__ __forceinline__ void cpasync_arrive(uint32_t bar) {
    asm volatile("cp.async.mbarrier.arrive.noinc.shared.b64 [%0];"
                 :: "r"(bar) : "memory");
}

#define TLD_X32(r, a)                                                          \
    asm volatile(                                                              \
        "tcgen05.ld.sync.aligned.32x32b.x32.b32 "                              \
        "{%0,%1,%2,%3,%4,%5,%6,%7,%8,%9,%10,%11,%12,%13,%14,%15,"              \
        "%16,%17,%18,%19,%20,%21,%22,%23,%24,%25,%26,%27,%28,%29,%30,%31}, [%32];" \
        : "=r"((r)[0]), "=r"((r)[1]), "=r"((r)[2]), "=r"((r)[3]),              \
          "=r"((r)[4]), "=r"((r)[5]), "=r"((r)[6]), "=r"((r)[7]),              \
          "=r"((r)[8]), "=r"((r)[9]), "=r"((r)[10]), "=r"((r)[11]),            \
          "=r"((r)[12]), "=r"((r)[13]), "=r"((r)[14]), "=r"((r)[15]),          \
          "=r"((r)[16]), "=r"((r)[17]), "=r"((r)[18]), "=r"((r)[19]),          \
          "=r"((r)[20]), "=r"((r)[21]), "=r"((r)[22]), "=r"((r)[23]),          \
          "=r"((r)[24]), "=r"((r)[25]), "=r"((r)[26]), "=r"((r)[27]),          \
          "=r"((r)[28]), "=r"((r)[29]), "=r"((r)[30]), "=r"((r)[31])           \
        : "r"(a))

#define TST_X32(a, r)                                                          \
    asm volatile(                                                              \
        "tcgen05.st.sync.aligned.32x32b.x32.b32 [%0], "                        \
        "{%1,%2,%3,%4,%5,%6,%7,%8,%9,%10,%11,%12,%13,%14,%15,%16,"             \
        "%17,%18,%19,%20,%21,%22,%23,%24,%25,%26,%27,%28,%29,%30,%31,%32};"    \
        :: "r"(a),                                                             \
           "r"((r)[0]), "r"((r)[1]), "r"((r)[2]), "r"((r)[3]),                 \
           "r"((r)[4]), "r"((r)[5]), "r"((r)[6]), "r"((r)[7]),                 \
           "r"((r)[8]), "r"((r)[9]), "r"((r)[10]), "r"((r)[11]),               \
           "r"((r)[12]), "r"((r)[13]), "r"((r)[14]), "r"((r)[15]),             \
           "r"((r)[16]), "r"((r)[17]), "r"((r)[18]), "r"((r)[19]),             \
           "r"((r)[20]), "r"((r)[21]), "r"((r)[22]), "r"((r)[23]),             \
           "r"((r)[24]), "r"((r)[25]), "r"((r)[26]), "r"((r)[27]),             \
           "r"((r)[28]), "r"((r)[29]), "r"((r)[30]), "r"((r)[31])              \
        : "memory")
#endif

// ================= GEMM: C = A(MxK) @ Bt(NxK)^T + bias ===================
// CTA tile 128x256, 2 physical SMEM stages (SW128, 32-float rows) treated
// as 4 pipeline units of K=16 (k-halves). cp.async + mbarrier producer/
// consumer (no per-iter __syncthreads). 2 CTAs/SM. ACT=1: silu + add[].
#define GBM 128
#define GBN 256
#define GBK 32
#define A_TILE_B (GBM*GBK*4)                 // 16384
#define B_TILE_B (GBN*GBK*4)                 // 32768
#define STAGE_B  (A_TILE_B + B_TILE_B)       // 49152
#define GSMEM_TOTAL (1024 + 2*STAGE_B)       // 99328

template<int ACT>
__global__ __launch_bounds__(256, 2)
void gemm_tc(const float* __restrict__ A, const float* __restrict__ Bt,
             const float* __restrict__ bias, const float* __restrict__ add,
             float* __restrict__ C, int M, int N, int K)
{
    extern __shared__ char sm_raw[];
    int tid = threadIdx.x;
    int m0 = blockIdx.y * GBM, n0 = blockIdx.x * GBN;

#if HAS_TCGEN05
    uint32_t sb = smem_u32(sm_raw);
    int wid = tid >> 5, lid = tid & 31;

    if (wid == 0)
        asm volatile("tcgen05.alloc.cta_group::1.sync.aligned.shared::cta.b32 [%0], %1;"
                     :: "r"(sb), "r"(256u) : "memory");
    if (tid == 0) {
        // done[0..3] @ sb+8..32 (count 1), full[0..3] @ sb+40..64 (count 256)
        #pragma unroll
        for (int i = 0; i < 4; i++) mbar_init(sb + 8 + 8 * i, 1);
        #pragma unroll
        for (int i = 0; i < 4; i++) mbar_init(sb + 40 + 8 * i, 256);
    }
    __syncthreads();
    uint32_t tmem;
    asm volatile("ld.shared.b32 %0, [%1];" : "=r"(tmem) : "r"(sb));
    if (wid == 0)
        asm volatile("tcgen05.relinquish_alloc_permit.cta_group::1.sync.aligned;");

    const uint32_t idesc = (1u << 4) | (2u << 7) | (2u << 10) |
                           ((GBN / 8) << 17) | ((GBM / 16) << 24);
    const int nu = K / 16;          // pipeline units (K=16 each)

    // unit u: physical stage sp=(u>>1)&1, k-half h=u&1, slot=u&3,
    // global k = u*16, smem columns (4h+f)*16 bytes, f in 0..3
    auto load_unit = [&](int u) {
        int sp = (u >> 1) & 1, h = u & 1, slot = u & 3;
        uint32_t tileA = sb + 1024 + sp * STAGE_B;
        uint32_t tileB = tileA + A_TILE_B;
        const float* Ab = A + (size_t)m0 * K + (size_t)u * 16;
        #pragma unroll
        for (int i = 0; i < 2; i++) {
            int idx = tid + i * 256;          // 0..511
            int m = idx >> 2, f = idx & 3;
            uint32_t off = m * 128 + (4 * h + f) * 16;
            uint32_t sw = off ^ ((off >> 3) & 0x70);
            cpasync16(tileA + sw, Ab + (size_t)m * K + f * 4);
        }
        const float* Bb = Bt + (size_t)n0 * K + (size_t)u * 16;
        #pragma unroll
        for (int i = 0; i < 4; i++) {
            int idx = tid + i * 256;          // 0..1023
            int n = idx >> 2, f = idx & 3;
            uint32_t off = n * 128 + (4 * h + f) * 16;
            uint32_t sw = off ^ ((off >> 3) & 0x70);
            cpasync16(tileB + sw, Bb + (size_t)n * K + f * 4);
        }
        cpasync_arrive(sb + 40 + 8 * slot);
    };

    bool lead = false;
    if (wid == 0) lead = (elect_one() != 0);

    uint32_t phF[4] = {0, 0, 0, 0};
    uint32_t phD[4] = {0, 0, 0, 0};

    load_unit(0); load_unit(1); load_unit(2); load_unit(3);

    for (int u = 0; u < nu; u++) {
        int slot = u & 3;
        if (lead) {
            mbar_wait(sb + 40 + 8 * slot, phF[slot]); phF[slot] ^= 1;
            asm volatile("fence.proxy.async.shared::cta;" ::: "memory");
            int sp = (u >> 1) & 1, h = u & 1;
            uint32_t tileA = sb + 1024 + sp * STAGE_B;
            uint64_t ad = make_desc_sw128(tileA) + 4 * h;
            uint64_t bd = make_desc_sw128(tileA + A_TILE_B) + 4 * h;
            #pragma unroll
            for (int kk = 0; kk < 2; kk++) {
                uint32_t en = (u > 0 || kk > 0) ? 1u : 0u;
                mma_tf32(tmem, ad + kk * 2, bd + kk * 2, idesc, en);
            }
            asm volatile(
                "tcgen05.commit.cta_group::1.mbarrier::arrive::one.shared::cluster.b64 [%0];"
                :: "r"(sb + 8 + 8 * slot) : "memory");
        }
        if (u + 4 < nu) {
            mbar_wait(sb + 8 + 8 * slot, phD[slot]); phD[slot] ^= 1;
            load_unit(u + 4);
        }
    }

    // drain: wait the final MMA (tensor queue is FIFO from one thread)
    {
        int slot = (nu - 1) & 3;
        mbar_wait(sb + 8 + 8 * slot, phD[slot]);
    }
    asm volatile("tcgen05.fence::after_thread_sync;" ::: "memory");

    if (wid < 4) {
        size_t row = (size_t)(m0 + wid * 32 + lid);
        #pragma unroll 1
        for (int c = 0; c < GBN / 32; c++) {
            uint32_t r[32];
            TLD_X32(r, tmem + c * 32);
            asm volatile("tcgen05.wait::ld.sync.aligned;" ::: "memory");

            int cb = n0 + c * 32;
            #pragma unroll
            for (int j = 0; j < 32; j += 4) {
                float4 bv = *reinterpret_cast<const float4*>(bias + cb + j);
                float4 o;
                o.x = __uint_as_float(r[j + 0]) + bv.x;
                o.y = __uint_as_float(r[j + 1]) + bv.y;
                o.z = __uint_as_float(r[j + 2]) + bv.z;
                o.w = __uint_as_float(r[j + 3]) + bv.w;
                if (ACT == 1) {
                    float4 av = *reinterpret_cast<const float4*>(
                        add + row * N + cb + j);
                    o.x = o.x / (1.f + expf(-o.x)) + av.x;
                    o.y = o.y / (1.f + expf(-o.y)) + av.y;
                    o.z = o.z / (1.f + expf(-o.z)) + av.z;
                    o.w = o.w / (1.f + expf(-o.w)) + av.w;
                }
                *reinterpret_cast<float4*>(C + row * N + cb + j) = o;
            }
        }
    }
    __syncthreads();
    if (wid == 0)
        asm volatile("tcgen05.dealloc.cta_group::1.sync.aligned.b32 %0, %1;"
                     :: "r"(tmem), "r"(256u));

#else   // ---------------- SIMT fallback (two 128x128 halves) --------------
    const int BK = 16;
    float* As = reinterpret_cast<float*>(sm_raw);
    float* Bs = As + 16 * 132;

    int ty = tid >> 4, tx = tid & 15;
    int aRow = tid >> 2, aCol = (tid & 3) << 2;

    for (int half = 0; half < 2; half++) {
        int n0h = n0 + half * 128;
        float acc[8][8];
        #pragma unroll
        for (int i = 0; i < 8; i++)
            #pragma unroll
            for (int j = 0; j < 8; j++) acc[i][j] = 0.f;

        for (int kt = 0; kt < K; kt += BK) {
            #pragma unroll
            for (int p = 0; p < 2; p++) {
                int r = aRow + p * 64;
                float4 v = *reinterpret_cast<const float4*>(
                    &A[(size_t)(m0 + r) * K + kt + aCol]);
                As[(aCol + 0) * 132 + r] = v.x;
                As[(aCol + 1) * 132 + r] = v.y;
                As[(aCol + 2) * 132 + r] = v.z;
                As[(aCol + 3) * 132 + r] = v.w;
            }
            #pragma unroll
            for (int p = 0; p < 2; p++) {
                int n = aRow + p * 64;
                float4 v = *reinterpret_cast<const float4*>(
                    &Bt[(size_t)(n0h + n) * K + kt + aCol]);
                Bs[(aCol + 0) * 132 + n] = v.x;
                Bs[(aCol + 1) * 132 + n] = v.y;
                Bs[(aCol + 2) * 132 + n] = v.z;
                Bs[(aCol + 3) * 132 + n] = v.w;
            }
            __syncthreads();
            #pragma unroll
            for (int k = 0; k < BK; k++) {
                float a[8], b[8];
                #pragma unroll
                for (int i = 0; i < 8; i++) a[i] = As[k * 132 + ty * 8 + i];
                #pragma unroll
                for (int j = 0; j < 8; j++) b[j] = Bs[k * 132 + tx * 8 + j];
                #pragma unroll
                for (int i = 0; i < 8; i++)
                    #pragma unroll
                    for (int j = 0; j < 8; j++)
                        acc[i][j] += a[i] * b[j];
            }
            __syncthreads();
        }

        #pragma unroll
        for (int i = 0; i < 8; i++) {
            size_t r = m0 + ty * 8 + i;
            #pragma unroll
            for (int j4 = 0; j4 < 2; j4++) {
                int c = n0h + tx * 8 + j4 * 4;
                float4 v;
                v.x = acc[i][j4 * 4 + 0] + bias[c + 0];
                v.y = acc[i][j4 * 4 + 1] + bias[c + 1];
                v.z = acc[i][j4 * 4 + 2] + bias[c + 2];
                v.w = acc[i][j4 * 4 + 3] + bias[c + 3];
                if (ACT == 1) {
                    float4 av = *reinterpret_cast<const float4*>(&add[r * N + c]);
                    v.x = v.x / (1.f + expf(-v.x)) + av.x;
                    v.y = v.y / (1.f + expf(-v.y)) + av.y;
                    v.z = v.z / (1.f + expf(-v.z)) + av.z;
                    v.w = v.w / (1.f + expf(-v.w)) + av.w;
                }
                *reinterpret_cast<float4*>(&C[r * N + c]) = v;
            }
        }
    }
#endif
}

// ---------------- prep kernels -------------------------------------------
__global__ __launch_bounds__(256)
void round_copy_kernel(const float* __restrict__ src, float* __restrict__ dst)
{
    int i = blockIdx.x * 256 + threadIdx.x;
    float4 v = reinterpret_cast<const float4*>(src)[i];
    v.x = roundtf(v.x); v.y = roundtf(v.y);
    v.z = roundtf(v.z); v.w = roundtf(v.w);
    reinterpret_cast<float4*>(dst)[i] = v;
}

__global__ __launch_bounds__(256)
void transpose_round_kernel(const float* __restrict__ src, float* __restrict__ dst,
                            int K, int N)
{
    __shared__ float t[32][33];
    int n0 = blockIdx.x * 32, k0 = blockIdx.y * 32;
    #pragma unroll
    for (int j = 0; j < 4; j++) {
        int k = k0 + threadIdx.y + 8 * j;
        t[threadIdx.y + 8 * j][threadIdx.x] = src[(size_t)k * N + n0 + threadIdx.x];
    }
    __syncthreads();
    #pragma unroll
    for (int j = 0; j < 4; j++) {
        int n = n0 + threadIdx.y + 8 * j;
        dst[(size_t)n * K + k0 + threadIdx.x] =
            roundtf(t[threadIdx.x][threadIdx.y + 8 * j]);
    }
}

// ---------------- RoPE (in-place, outputs rounded to tf32 grid) ----------
__global__ __launch_bounds__(256)
void rope_kernel(float* __restrict__ fused, const float* __restrict__ rope_w)
{
    int idx = blockIdx.x * blockDim.x + threadIdx.x;
    int i = idx & 63;
    int h = (idx >> 6) & 15;
    int s = (idx >> 10) & 2047;
    int b = idx >> 21;

    float* base = fused + (size_t)(b * Sv + s) * N_FUSED + h * DHv;
    float c0, s0, c1, s1;
    sincosf(rope_w[s * DHv + i],      &s0, &c0);
    sincosf(rope_w[s * DHv + i + 64], &s1, &c1);
    const float rs = 0.08838834764831845f;

    float q0 = base[i], q1 = base[i + 64];
    base[i]      = roundtf((q0 * c0 + q1 * s0) * rs);
    base[i + 64] = roundtf((q1 * c1 + q0 * s1) * rs);

    float k0 = base[Dv + i], k1 = base[Dv + i + 64];
    base[Dv + i]      = roundtf(k0 * c0 + k1 * s0);
    base[Dv + i + 64] = roundtf(k1 * c1 + k0 * s1);
}

// ---------------- Flash attention: tcgen05 tf32 (R9-passing) --------------
#define AT_Q    1024
#define AT_K    (AT_Q + 65536)
#define AT_V    (AT_K + 65536)
#define AT_P    (AT_V + 32768)
#define ASMEM_TOTAL (AT_P + 32768)

__global__ __launch_bounds__(128, 1)
void attn_tc(const float* __restrict__ fused)
{
    extern __shared__ char sm_raw[];
    int tid = threadIdx.x;
    int qt = 15 - blockIdx.x;             // big tiles first
    int bh = blockIdx.y;
    int b = bh >> 4, h = bh & 15;
    const float* qbase = fused + (size_t)b * Sv * N_FUSED + h * DHv;
    const float* kbase = qbase + Dv;
    const float* vbase = qbase + 2 * Dv;

#if HAS_TCGEN05
    uint32_t sb = smem_u32(sm_raw);
    int wid = tid >> 5, lid = tid & 31;

    if (wid == 0)
        asm volatile("tcgen05.alloc.cta_group::1.sync.aligned.shared::cta.b32 [%0], %1;"
                     :: "r"(sb), "r"(256u) : "memory");
    if (tid == 0) { mbar_init(sb + 8, 1); mbar_init(sb + 16, 1); }
    __syncthreads();
    uint32_t tmem;
    asm volatile("ld.shared.b32 %0, [%1];" : "=r"(tmem) : "r"(sb));
    if (wid == 0)
        asm volatile("tcgen05.relinquish_alloc_permit.cta_group::1.sync.aligned;");

    uint32_t TS = tmem;          // S: cols 0-63
    uint32_t TO = tmem + 64;     // O: cols 64-191

    for (int u = tid; u < 4096; u += 128) {
        int c = u >> 10;
        int rem = u & 1023;
        int r = rem >> 3, f4 = rem & 7;
        uint32_t off = r * 128 + f4 * 16;
        off ^= (off >> 3) & 0x70;
        cpasync16(sb + AT_Q + c * 16384 + off,
                  qbase + (size_t)(qt * 128 + r) * N_FUSED + c * 32 + f4 * 4);
    }
    auto loadK = [&](int kt, int buf) {
        const float* kb2 = kbase + (size_t)(kt * 64) * N_FUSED;
        for (int u = tid; u < 2048; u += 128) {
            int c = u >> 9;
            int rem = u & 511;
            int r = rem >> 3, f4 = rem & 7;
            uint32_t off = r * 128 + f4 * 16;
            off ^= (off >> 3) & 0x70;
            cpasync16(sb + AT_K + buf * 32768 + c * 8192 + off,
                      kb2 + (size_t)r * N_FUSED + c * 32 + f4 * 4);
        }
        asm volatile("cp.async.commit_group;" ::: "memory");
    };
    loadK(0, 0);

    const int nkv = 2 * qt + 2;
    const uint32_t idescS = (1u << 4) | (2u << 7) | (2u << 10) |
                            (8u << 17) | (8u << 24);
    const uint32_t idescO = (1u << 4) | (2u << 7) | (2u << 10) |
                            (16u << 17) | (8u << 24);

    float m_run = -1e30f, l_run = 0.f;
    uint32_t phS = 0, phPV = 0;
    int qrow = qt * 128 + tid;

    for (int kt = 0; kt < nkv; kt++) {
        int kb = kt & 1;
        asm volatile("cp.async.wait_group 0;" ::: "memory");
        asm volatile("fence.proxy.async.shared::cta;" ::: "memory");
        __syncthreads();

        if (wid == 0 && elect_one()) {
            #pragma unroll
            for (int c = 0; c < 4; c++) {
                uint64_t ad = make_desc_sw128(sb + AT_Q + c * 16384);
                uint64_t bd = make_desc_sw128(sb + AT_K + kb * 32768 + c * 8192);
                #pragma unroll
                for (int kk = 0; kk < 4; kk++)
                    mma_tf32(TS, ad + kk * 2, bd + kk * 2, idescS,
                             (c > 0 || kk > 0) ? 1u : 0u);
            }
            asm volatile(
                "tcgen05.commit.cta_group::1.mbarrier::arrive::one.shared::cluster.b64 [%0];"
                :: "r"(sb + 8) : "memory");
        }

        if (kt + 1 < nkv) loadK(kt + 1, kb ^ 1);

        if (kt > 0) {
            mbar_wait(sb + 16, phPV); phPV ^= 1;
            asm volatile("tcgen05.fence::after_thread_sync;" ::: "memory");
        }

        {
            const float* vb2 = vbase + (size_t)(kt * 64) * N_FUSED;
            #pragma unroll
            for (int ch = 0; ch < 2; ch++) {
                #pragma unroll
                for (int g = 0; g < 2; g++) {
                    int kvq = ch * 32 + g * 16 + wid * 4;
                    #pragma unroll
                    for (int i = 0; i < 4; i++) {
                        int dh = lid + 32 * i;
                        uint32_t v0 = f2tf32(vb2[(size_t)(kvq + 0) * N_FUSED + dh]);
                        uint32_t v1 = f2tf32(vb2[(size_t)(kvq + 1) * N_FUSED + dh]);
                        uint32_t v2 = f2tf32(vb2[(size_t)(kvq + 2) * N_FUSED + dh]);
                        uint32_t v3 = f2tf32(vb2[(size_t)(kvq + 3) * N_FUSED + dh]);
                        uint32_t off = dh * 128 + g * 64 + wid * 16;
                        off ^= (off >> 3) & 0x70;
                        asm volatile("st.shared.v4.b32 [%0], {%1,%2,%3,%4};"
                                     :: "r"(sb + AT_V + ch * 16384 + off),
                                        "r"(v0), "r"(v1), "r"(v2), "r"(v3)
                                     : "memory");
                    }
                }
            }
        }

        mbar_wait(sb + 8, phS); phS ^= 1;
        asm volatile("tcgen05.fence::after_thread_sync;" ::: "memory");

        float sv[64];
        {
            uint32_t rr[32];
            TLD_X32(rr, TS);
            asm volatile("tcgen05.wait::ld.sync.aligned;" ::: "memory");
            int kvb = kt * 64;
            #pragma unroll
            for (int j = 0; j < 32; j++)
                sv[j] = (kvb + j > qrow) ? -1e30f : __uint_as_float(rr[j]);
            TLD_X32(rr, TS + 32);
            asm volatile("tcgen05.wait::ld.sync.aligned;" ::: "memory");
            #pragma unroll
            for (int j = 0; j < 32; j++)
                sv[32 + j] = (kvb + 32 + j > qrow) ? -1e30f : __uint_as_float(rr[j]);
        }
        float mx = m_run;
        #pragma unroll
        for (int j = 0; j < 64; j++) mx = fmaxf(mx, sv[j]);
        float alpha = __expf(m_run - mx);
        float ssum = 0.f;
        #pragma unroll
        for (int j = 0; j < 64; j++) {
            float p = roundtf(__expf(sv[j] - mx));
            sv[j] = p;
            ssum += p;
        }
        l_run = l_run * alpha + ssum;
        m_run = mx;

        #pragma unroll
        for (int ch = 0; ch < 2; ch++) {
            #pragma unroll
            for (int f4 = 0; f4 < 8; f4++) {
                uint32_t off = tid * 128 + f4 * 16;
                off ^= (off >> 3) & 0x70;
                int j = ch * 32 + f4 * 4;
                asm volatile("st.shared.v4.b32 [%0], {%1,%2,%3,%4};"
                             :: "r"(sb + AT_P + ch * 16384 + off),
                                "r"(__float_as_uint(sv[j + 0])),
                                "r"(__float_as_uint(sv[j + 1])),
                                "r"(__float_as_uint(sv[j + 2])),
                                "r"(__float_as_uint(sv[j + 3]))
                             : "memory");
            }
        }

        if (kt > 0) {
            uint32_t allone = __all_sync(0xffffffffu, alpha == 1.0f);
            if (!allone) {
                #pragma unroll 1
                for (int c2 = 0; c2 < 4; c2++) {
                    uint32_t rr[32];
                    TLD_X32(rr, TO + c2 * 32);
                    asm volatile("tcgen05.wait::ld.sync.aligned;" ::: "memory");
                    #pragma unroll
                    for (int j = 0; j < 32; j++)
                        rr[j] = __float_as_uint(__uint_as_float(rr[j]) * alpha);
                    TST_X32(TO + c2 * 32, rr);
                }
                asm volatile("tcgen05.wait::st.sync.aligned;" ::: "memory");
            }
        }
        asm volatile("tcgen05.fence::before_thread_sync;" ::: "memory");
        asm volatile("fence.proxy.async.shared::cta;" ::: "memory");
        __syncthreads();

        if (wid == 0 && elect_one()) {
            asm volatile("tcgen05.fence::after_thread_sync;" ::: "memory");
            #pragma unroll
            for (int ch = 0; ch < 2; ch++) {
                uint64_t ad = make_desc_sw128(sb + AT_P + ch * 16384);
                uint64_t bd = make_desc_sw128(sb + AT_V + ch * 16384);
                #pragma unroll
                for (int kk = 0; kk < 4; kk++)
                    mma_tf32(TO, ad + kk * 2, bd + kk * 2, idescO,
                             (kt > 0 || ch > 0 || kk > 0) ? 1u : 0u);
            }
            asm volatile(
                "tcgen05.commit.cta_group::1.mbarrier::arrive::one.shared::cluster.b64 [%0];"
                :: "r"(sb + 16) : "memory");
        }
    }

    mbar_wait(sb + 16, phPV);
    asm volatile("tcgen05.fence::after_thread_sync;" ::: "memory");

    float inv = 1.f / l_run;
    size_t ob = (size_t)(b * Sv + qt * 128 + tid) * Dv + h * DHv;
    #pragma unroll 1
    for (int c2 = 0; c2 < 4; c2++) {
        uint32_t rr[32];
        TLD_X32(rr, TO + c2 * 32);
        asm volatile("tcgen05.wait::ld.sync.aligned;" ::: "memory");
        #pragma unroll
        for (int j = 0; j < 32; j += 4) {
            float4 v;
            v.x = roundtf(__uint_as_float(rr[j + 0]) * inv);
            v.y = roundtf(__uint_as_float(rr[j + 1]) * inv);
            v.z = roundtf(__uint_as_float(rr[j + 2]) * inv);
            v.w = roundtf(__uint_as_float(rr[j + 3]) * inv);
            *reinterpret_cast<float4*>(&g_o[ob + c2 * 32 + j]) = v;
        }
    }
    __syncthreads();
    if (wid == 0)
        asm volatile("tcgen05.dealloc.cta_group::1.sync.aligned.b32 %0, %1;"
                     :: "r"(tmem), "r"(256u));

#else  // SIMT fallback
    float* Qs = reinterpret_cast<float*>(sm_raw);
    float* Ks = Qs + 128 * 128;
    float* Vs = Ks + 32 * 128;

    for (int u = tid; u < 128 * 32; u += 128) {
        int r = u >> 5, c4 = (u & 31) << 2;
        float4 v = *reinterpret_cast<const float4*>(
            &qbase[(size_t)(qt * 128 + r) * N_FUSED + c4]);
        *reinterpret_cast<float4*>(&Qs[r * 128 + c4]) = v;
    }
    float O[128];
    #pragma unroll
    for (int d = 0; d < 128; d++) O[d] = 0.f;
    float m = -1e30f, l = 0.f;
    int qglob = qt * 128 + tid;
    int nkv = (qt + 1) * 128 / 32;

    for (int kvt = 0; kvt < nkv; kvt++) {
        __syncthreads();
        for (int u = tid; u < 32 * 32; u += 128) {
            int r = u >> 5, c4 = (u & 31) << 2;
            *reinterpret_cast<float4*>(&Ks[r * 128 + c4]) =
                *reinterpret_cast<const float4*>(
                    &kbase[(size_t)(kvt * 32 + r) * N_FUSED + c4]);
            *reinterpret_cast<float4*>(&Vs[r * 128 + c4]) =
                *reinterpret_cast<const float4*>(
                    &vbase[(size_t)(kvt * 32 + r) * N_FUSED + c4]);
        }
        __syncthreads();
        for (int j = 0; j < 32; j++) {
            int kv = kvt * 32 + j;
            float s = -1e30f;
            if (kv <= qglob) {
                s = 0.f;
                for (int k = 0; k < 128; k++)
                    s += Qs[tid * 128 + k] * Ks[j * 128 + k];
            }
            float mn = fmaxf(m, s);
            float a = __expf(m - mn);
            float p = __expf(s - mn);
            l = l * a + p;
            m = mn;
            for (int d = 0; d < 128; d++)
                O[d] = O[d] * a + p * Vs[j * 128 + d];
        }
    }
    float inv = 1.f / l;
    size_t ob = (size_t)(b * Sv + qt * 128 + tid) * Dv + h * DHv;
    for (int d = 0; d < 128; d++)
        g_o[ob + d] = roundtf(O[d] * inv);
#endif
}

// ---------------- block reduction helper ----------------------------------
__device__ __forceinline__ float block_sum256(float v)
{
    __shared__ float red[8];
    int t = threadIdx.x;
    #pragma unroll
    for (int o = 16; o > 0; o >>= 1)
        v += __shfl_xor_sync(0xffffffffu, v, o);
    if ((t & 31) == 0) red[t >> 5] = v;
    __syncthreads();
    float total = 0.f;
    #pragma unroll
    for (int i = 0; i < 8; i++) total += red[i];
    __syncthreads();
    return total;
}

// ---------------- LayerNorm(ff) + ReLU (float4 vectorized) ----------------
__global__ __launch_bounds__(256)
void ln_relu_kernel(const float* __restrict__ fused,
                    const float* __restrict__ gamma,
                    const float* __restrict__ beta,
                    float* __restrict__ out)
{
    int row = blockIdx.x;
    const float4* x4 = reinterpret_cast<const float4*>(
        fused + (size_t)row * N_FUSED + 3 * Dv);
    float4 v[8];
    float s = 0.f;
    #pragma unroll
    for (int i = 0; i < 8; i++) {
        v[i] = x4[threadIdx.x + (i << 8)];
        s += (v[i].x + v[i].y) + (v[i].z + v[i].w);
    }
    float mean = block_sum256(s) * (1.0f / FFv);
    float s2 = 0.f;
    #pragma unroll
    for (int i = 0; i < 8; i++) {
        float dx = v[i].x - mean, dy = v[i].y - mean;
        float dz = v[i].z - mean, dw = v[i].w - mean;
        s2 += (dx * dx + dy * dy) + (dz * dz + dw * dw);
    }
    float var = block_sum256(s2) * (1.0f / FFv);
    float rstd = rsqrtf(var + EPSv);
    float4* o4 = reinterpret_cast<float4*>(out + (size_t)row * FFv);
    const float4* g4 = reinterpret_cast<const float4*>(gamma);
    const float4* b4 = reinterpret_cast<const float4*>(beta);
    #pragma unroll
    for (int i = 0; i < 8; i++) {
        int c = threadIdx.x + (i << 8);
        float4 g = g4[c], bb = b4[c], o;
        o.x = roundtf(fmaxf(g.x * (v[i].x - mean) * rstd + bb.x, 0.f));
        o.y = roundtf(fmaxf(g.y * (v[i].y - mean) * rstd + bb.y, 0.f));
        o.z = roundtf(fmaxf(g.z * (v[i].z - mean) * rstd + bb.z, 0.f));
        o.w = roundtf(fmaxf(g.w * (v[i].w - mean) * rstd + bb.w, 0.f));
        o4[c] = o;
    }
}

// ---------------- final: LayerNorm(sum) (float4 vectorized) ---------------
__global__ __launch_bounds__(256)
void ln_final_kernel(const float* __restrict__ src,
                     const float* __restrict__ gamma,
                     const float* __restrict__ beta,
                     float* __restrict__ out)
{
    int row = blockIdx.x;
    const float4* x4 = reinterpret_cast<const float4*>(src + (size_t)row * Dv);
    float4 v[2];
    float s = 0.f;
    #pragma unroll
    for (int i = 0; i < 2; i++) {
        v[i] = x4[threadIdx.x + (i << 8)];
        s += (v[i].x + v[i].y) + (v[i].z + v[i].w);
    }
    float mean = block_sum256(s) * (1.0f / Dv);
    float s2 = 0.f;
    #pragma unroll
    for (int i = 0; i < 2; i++) {
        float dx = v[i].x - mean, dy = v[i].y - mean;
        float dz = v[i].z - mean, dw = v[i].w - mean;
        s2 += (dx * dx + dy * dy) + (dz * dz + dw * dw);
    }
    float var = block_sum256(s2) * (1.0f / Dv);
    float rstd = rsqrtf(var + EPSv);
    float4* o4 = reinterpret_cast<float4*>(out + (size_t)row * Dv);
    const float4* g4 = reinterpret_cast<const float4*>(gamma);
    const float4* b4 = reinterpret_cast<const float4*>(beta);
    #pragma unroll
    for (int i = 0; i < 2; i++) {
        int c = threadIdx.x + (i << 8);
        float4 g = g4[c], bb = b4[c], o;
        o.x = g.x * (v[i].x - mean) * rstd + bb.x;
        o.y = g.y * (v[i].y - mean) * rstd + bb.y;
        o.z = g.z * (v[i].z - mean) * rstd + bb.z;
        o.w = g.w * (v[i].w - mean) * rstd + bb.w;
        o4[c] = o;
    }
}

// ---------------- launch ---------------------------------------------------
extern "C" void kernel_launch(void* const* d_in, const int* in_sizes, int n_in,
                              void* d_out, int out_size)
{
    const float* x       = (const float*)d_in[0];
    const float* W_fused = (const float*)d_in[1];
    const float* b_fused = (const float*)d_in[2];
    const float* W_attn  = (const float*)d_in[3];
    const float* b_attn  = (const float*)d_in[4];
    const float* W_ff    = (const float*)d_in[5];
    const float* b_ff    = (const float*)d_in[6];
    const float* gamma1  = (const float*)d_in[7];
    const float* beta1   = (const float*)d_in[8];
    const float* gamma2  = (const float*)d_in[9];
    const float* beta2   = (const float*)d_in[10];
    const float* rope_w  = (const float*)d_in[11];
    float* out = (float*)d_out;
    (void)in_sizes; (void)n_in; (void)out_size;

    float *fused, *o, *attn, *h, *ffo, *xr, *wfT, *waT, *ffT;
    cudaGetSymbolAddress((void**)&fused, g_fused);
    cudaGetSymbolAddress((void**)&o,     g_o);
    cudaGetSymbolAddress((void**)&attn,  g_attn);
    cudaGetSymbolAddress((void**)&h,     g_h);
    cudaGetSymbolAddress((void**)&ffo,   g_ffo);
    cudaGetSymbolAddress((void**)&xr,    g_xr);
    cudaGetSymbolAddress((void**)&wfT,   g_wfT);
    cudaGetSymbolAddress((void**)&waT,   g_waT);
    cudaGetSymbolAddress((void**)&ffT,   g_ffT);

    cudaFuncSetAttribute(gemm_tc<0>,
        cudaFuncAttributeMaxDynamicSharedMemorySize, GSMEM_TOTAL);
    cudaFuncSetAttribute(gemm_tc<1>,
        cudaFuncAttributeMaxDynamicSharedMemorySize, GSMEM_TOTAL);
    cudaFuncSetAttribute(attn_tc,
        cudaFuncAttributeMaxDynamicSharedMemorySize, ASMEM_TOTAL);

    // 0. prep
    round_copy_kernel<<<(M_TOT * Dv / 4) / 256, 256>>>(x, xr);
    transpose_round_kernel<<<dim3(N_FUSED / 32, Dv / 32), dim3(32, 8)>>>(
        W_fused, wfT, Dv, N_FUSED);
    transpose_round_kernel<<<dim3(Dv / 32, Dv / 32), dim3(32, 8)>>>(
        W_attn, waT, Dv, Dv);
    transpose_round_kernel<<<dim3(Dv / 32, FFv / 32), dim3(32, 8)>>>(
        W_ff, ffT, FFv, Dv);

    // 1. fused = x @ W_fused + b_fused
    gemm_tc<0><<<dim3(N_FUSED / GBN, M_TOT / GBM), 256, GSMEM_TOTAL>>>(
        xr, wfT, b_fused, nullptr, fused, M_TOT, N_FUSED, Dv);

    // 2. RoPE
    rope_kernel<<<(Bv * Sv * Hv * 64) / 256, 256>>>(fused, rope_w);

    // 3. Flash attention (tcgen05) -> g_o
    attn_tc<<<dim3(16, Bv * Hv), 128, ASMEM_TOTAL>>>(fused);

    // 4. attn = o @ W_attn + b_attn
    gemm_tc<0><<<dim3(Dv / GBN, M_TOT / GBM), 256, GSMEM_TOTAL>>>(
        o, waT, b_attn, nullptr, attn, M_TOT, Dv, Dv);

    // 5. h = relu(LN1(ff))
    ln_relu_kernel<<<M_TOT, 256>>>(fused, gamma1, beta1, h);

    // 6. ffo = silu(h @ W_ff + b_ff) + attn
    gemm_tc<1><<<dim3(Dv / GBN, M_TOT / GBM), 256, GSMEM_TOTAL>>>(
        h, ffT, b_ff, attn, ffo, M_TOT, Dv, FFv);

    // 7. out = LN2(ffo)
    ln_final_kernel<<<M_TOT, 256>>>(ffo, gamma2, beta2, out);
}

// round 14
// speedup vs baseline: 1.5124x; 1.5124x over previous
#include <cuda_runtime.h>
#include <cstdint>
#include <math.h>

#define Bv 2
#define Sv 2048
#define Dv 2048
#define Hv 16
#define DHv 128
#define FFv 8192
#define M_TOT (Bv*Sv)            // 4096
#define N_FUSED (3*Dv + FFv)     // 14336
#define EPSv 1e-6f

#if defined(__CUDA_ARCH__) && (defined(__CUDA_ARCH_FEAT_SM103_ALL) || defined(__CUDA_ARCH_SPECIFIC__))
#define HAS_TCGEN05 1
#else
#define HAS_TCGEN05 0
#endif

// ---------------- scratch (static device globals; no allocations) --------
__device__ float g_fused[58720256];   // 4096 x 14336
__device__ float g_o[8388608];        // 4096 x 2048   (tf32-rounded)
__device__ float g_attn[8388608];     // 4096 x 2048
__device__ float g_h[33554432];       // 4096 x 8192   (tf32-rounded)
__device__ float g_ffo[8388608];      // 4096 x 2048   (attn + silu(ff))
__device__ float g_xr[8388608];       // 4096 x 2048   rounded x
__device__ float g_wfT[29360128];     // 14336 x 2048  W_fused^T rounded
__device__ float g_waT[4194304];      // 2048 x 2048   W_attn^T rounded
__device__ float g_ffT[16777216];     // 2048 x 8192   W_ff^T rounded

// ================= helpers ================================================
__device__ __forceinline__ uint32_t smem_u32(const void* p) {
    uint32_t a;
    asm("{ .reg .u64 t; cvta.to.shared.u64 t, %1; cvt.u32.u64 %0, t; }"
        : "=r"(a) : "l"(p));
    return a;
}
__device__ __forceinline__ uint32_t f2tf32(float x) {
    return (__float_as_uint(x) + 0x1000u) & 0xFFFFE000u;
}
__device__ __forceinline__ float roundtf(float x) {
    return __uint_as_float(f2tf32(x));
}

#if HAS_TCGEN05
__device__ __forceinline__ uint32_t elect_one() {
    uint32_t pred;
    asm volatile("{\n\t.reg .pred p;\n\telect.sync _|p, 0xFFFFFFFF;\n\t"
                 "selp.b32 %0, 1, 0, p;\n\t}" : "=r"(pred));
    return pred;
}
__device__ __forceinline__ void mbar_init(uint32_t a, uint32_t cnt) {
    asm volatile("mbarrier.init.shared.b64 [%0], %1;" :: "r"(a), "r"(cnt) : "memory");
}
__device__ __forceinline__ void mbar_wait(uint32_t a, uint32_t parity) {
    asm volatile(
        "{\n\t.reg .pred P;\n\t"
        "W%=:\n\t"
        "mbarrier.try_wait.parity.acquire.cta.shared::cta.b64 P, [%0], %1, 0x989680;\n\t"
        "@!P bra W%=;\n\t}"
        :: "r"(a), "r"(parity) : "memory");
}
__device__ __forceinline__ uint64_t make_desc_sw128(uint32_t addr) {
    const uint64_t base =
        (uint64_t(2)  << 61) | (uint64_t(1) << 46) |
        (uint64_t(64) << 32) | (uint64_t(1) << 16);
    return base | ((uint64_t)(addr >> 4) & 0x3FFF);
}
__device__ __forceinline__ void mma_tf32(uint32_t d, uint64_t ad, uint64_t bd,
                                         uint32_t idesc, uint32_t en) {
    asm volatile(
        "{\n\t.reg .pred p;\n\t"
        "setp.ne.u32 p, %4, 0;\n\t"
        "tcgen05.mma.cta_group::1.kind::tf32 [%0], %1, %2, %3, {%5, %5, %5, %5}, p;\n\t}"
        :: "r"(d), "l"(ad), "l"(bd), "r"(idesc), "r"(en), "r"(0u) : "memory");
}
__device__ __forceinline__ void cpasync16(uint32_t dst, const void* src) {
    asm volatile("cp.async.cg.shared.global [%0], [%1], 16;"
                 :: "r"(dst), "l"(src) : "memory");
}

#define TLD_X32(r, a)                                                          \
    asm volatile(                                                              \
        "tcgen05.ld.sync.aligned.32x32b.x32.b32 "                              \
        "{%0,%1,%2,%3,%4,%5,%6,%7,%8,%9,%10,%11,%12,%13,%14,%15,"              \
        "%16,%17,%18,%19,%20,%21,%22,%23,%24,%25,%26,%27,%28,%29,%30,%31}, [%32];" \
        : "=r"((r)[0]), "=r"((r)[1]), "=r"((r)[2]), "=r"((r)[3]),              \
          "=r"((r)[4]), "=r"((r)[5]), "=r"((r)[6]), "=r"((r)[7]),              \
          "=r"((r)[8]), "=r"((r)[9]), "=r"((r)[10]), "=r"((r)[11]),            \
          "=r"((r)[12]), "=r"((r)[13]), "=r"((r)[14]), "=r"((r)[15]),          \
          "=r"((r)[16]), "=r"((r)[17]), "=r"((r)[18]), "=r"((r)[19]),          \
          "=r"((r)[20]), "=r"((r)[21]), "=r"((r)[22]), "=r"((r)[23]),          \
          "=r"((r)[24]), "=r"((r)[25]), "=r"((r)[26]), "=r"((r)[27]),          \
          "=r"((r)[28]), "=r"((r)[29]), "=r"((r)[30]), "=r"((r)[31])           \
        : "r"(a))

#define TST_X32(a, r)                                                          \
    asm volatile(                                                              \
        "tcgen05.st.sync.aligned.32x32b.x32.b32 [%0], "                        \
        "{%1,%2,%3,%4,%5,%6,%7,%8,%9,%10,%11,%12,%13,%14,%15,%16,"             \
        "%17,%18,%19,%20,%21,%22,%23,%24,%25,%26,%27,%28,%29,%30,%31,%32};"    \
        :: "r"(a),                                                             \
           "r"((r)[0]), "r"((r)[1]), "r"((r)[2]), "r"((r)[3]),                 \
           "r"((r)[4]), "r"((r)[5]), "r"((r)[6]), "r"((r)[7]),                 \
           "r"((r)[8]), "r"((r)[9]), "r"((r)[10]), "r"((r)[11]),               \
           "r"((r)[12]), "r"((r)[13]), "r"((r)[14]), "r"((r)[15]),             \
           "r"((r)[16]), "r"((r)[17]), "r"((r)[18]), "r"((r)[19]),             \
           "r"((r)[20]), "r"((r)[21]), "r"((r)[22]), "r"((r)[23]),             \
           "r"((r)[24]), "r"((r)[25]), "r"((r)[26]), "r"((r)[27]),             \
           "r"((r)[28]), "r"((r)[29]), "r"((r)[30]), "r"((r)[31])              \
        : "memory")
#endif

// ================= GEMM: C = A(MxK) @ Bt(NxK)^T + bias ===================
// R9/R11-proven config: CTA tile 128x256, BK=32, 2-stage cp.async pipeline,
// tcgen05 MMA, 2 CTAs/SM. 8-warp epilogue (warps 0-3: cols 0-127, warps
// 4-7: cols 128-255; subpartition = wid&3). ACT=1: silu then + add[].
#define GBM 128
#define GBN 256
#define GBK 32
#define A_TILE_B (GBM*GBK*4)                 // 16384
#define B_TILE_B (GBN*GBK*4)                 // 32768
#define STAGE_B  (A_TILE_B + B_TILE_B)       // 49152
#define GSMEM_TOTAL (1024 + 2*STAGE_B)       // 99328

template<int ACT>
__global__ __launch_bounds__(256, 2)
void gemm_tc(const float* __restrict__ A, const float* __restrict__ Bt,
             const float* __restrict__ bias, const float* __restrict__ add,
             float* __restrict__ C, int M, int N, int K)
{
    extern __shared__ char sm_raw[];
    int tid = threadIdx.x;
    int m0 = blockIdx.y * GBM, n0 = blockIdx.x * GBN;

#if HAS_TCGEN05
    uint32_t sb = smem_u32(sm_raw);
    int wid = tid >> 5, lid = tid & 31;

    if (wid == 0)
        asm volatile("tcgen05.alloc.cta_group::1.sync.aligned.shared::cta.b32 [%0], %1;"
                     :: "r"(sb), "r"(256u) : "memory");
    if (tid == 0) { mbar_init(sb + 8, 1); mbar_init(sb + 16, 1); }
    __syncthreads();
    uint32_t tmem;
    asm volatile("ld.shared.b32 %0, [%1];" : "=r"(tmem) : "r"(sb));
    if (wid == 0)
        asm volatile("tcgen05.relinquish_alloc_permit.cta_group::1.sync.aligned;");

    const uint32_t idesc = (1u << 4) | (2u << 7) | (2u << 10) |
                           ((GBN / 8) << 17) | ((GBM / 16) << 24);
    const int nk = K / GBK;

    auto load_stage = [&](int it, int s) {
        uint32_t tileA = sb + 1024 + s * STAGE_B;
        uint32_t tileB = tileA + A_TILE_B;
        const float* Ab = A + (size_t)m0 * K + (size_t)it * GBK;
        #pragma unroll
        for (int i = 0; i < 4; i++) {
            int idx = tid + i * 256;
            int m = idx >> 3, f4 = idx & 7;
            uint32_t off = m * 128 + f4 * 16;
            uint32_t sw = off ^ ((off >> 3) & 0x70);
            cpasync16(tileA + sw, Ab + (size_t)m * K + f4 * 4);
        }
        const float* Bb = Bt + (size_t)n0 * K + (size_t)it * GBK;
        #pragma unroll
        for (int i = 0; i < 8; i++) {
            int idx = tid + i * 256;
            int n = idx >> 3, f4 = idx & 7;
            uint32_t off = n * 128 + f4 * 16;
            uint32_t sw = off ^ ((off >> 3) & 0x70);
            cpasync16(tileB + sw, Bb + (size_t)n * K + f4 * 4);
        }
        asm volatile("cp.async.commit_group;" ::: "memory");
    };

    uint32_t ph0 = 0, ph1 = 0;
    load_stage(0, 0);

    for (int it = 0; it < nk; it++) {
        int s = it & 1;
        if (it + 1 < nk) {
            int s2 = (it + 1) & 1;
            if (it >= 1) {
                if (s2 == 0) { mbar_wait(sb + 8,  ph0); ph0 ^= 1; }
                else         { mbar_wait(sb + 16, ph1); ph1 ^= 1; }
            }
            load_stage(it + 1, s2);
            asm volatile("cp.async.wait_group 1;" ::: "memory");
        } else {
            asm volatile("cp.async.wait_group 0;" ::: "memory");
        }
        asm volatile("fence.proxy.async.shared::cta;" ::: "memory");
        __syncthreads();

        if (wid == 0 && elect_one()) {
            uint32_t tileA = sb + 1024 + s * STAGE_B;
            uint64_t ad = make_desc_sw128(tileA);
            uint64_t bd = make_desc_sw128(tileA + A_TILE_B);
            #pragma unroll
            for (int kk = 0; kk < 4; kk++) {
                uint32_t en = (it > 0 || kk > 0) ? 1u : 0u;
                mma_tf32(tmem, ad + kk * 2, bd + kk * 2, idesc, en);
            }
            uint32_t mb = (s == 0) ? sb + 8 : sb + 16;
            asm volatile(
                "tcgen05.commit.cta_group::1.mbarrier::arrive::one.shared::cluster.b64 [%0];"
                :: "r"(mb) : "memory");
        }
    }

    if (((nk - 1) & 1) == 0) mbar_wait(sb + 8,  ph0);
    else                     mbar_wait(sb + 16, ph1);
    asm volatile("tcgen05.fence::after_thread_sync;" ::: "memory");

    // 8-warp epilogue: sub = wid&3 (rows), half = wid>>2 (column half)
    {
        int sub = wid & 3, half = wid >> 2;
        size_t row = (size_t)(m0 + sub * 32 + lid);
        uint32_t tcol = tmem + half * 128;
        int ncol = n0 + half * 128;
        #pragma unroll 1
        for (int c = 0; c < 4; c++) {
            uint32_t r[32];
            TLD_X32(r, tcol + c * 32);
            asm volatile("tcgen05.wait::ld.sync.aligned;" ::: "memory");

            int cb = ncol + c * 32;
            #pragma unroll
            for (int j = 0; j < 32; j += 4) {
                float4 bv = *reinterpret_cast<const float4*>(bias + cb + j);
                float4 o;
                o.x = __uint_as_float(r[j + 0]) + bv.x;
                o.y = __uint_as_float(r[j + 1]) + bv.y;
                o.z = __uint_as_float(r[j + 2]) + bv.z;
                o.w = __uint_as_float(r[j + 3]) + bv.w;
                if (ACT == 1) {
                    float4 av = *reinterpret_cast<const float4*>(
                        add + row * N + cb + j);
                    o.x = o.x / (1.f + expf(-o.x)) + av.x;
                    o.y = o.y / (1.f + expf(-o.y)) + av.y;
                    o.z = o.z / (1.f + expf(-o.z)) + av.z;
                    o.w = o.w / (1.f + expf(-o.w)) + av.w;
                }
                *reinterpret_cast<float4*>(C + row * N + cb + j) = o;
            }
        }
    }
    __syncthreads();
    if (wid == 0)
        asm volatile("tcgen05.dealloc.cta_group::1.sync.aligned.b32 %0, %1;"
                     :: "r"(tmem), "r"(256u));

#else   // ---------------- SIMT fallback (two 128x128 halves) --------------
    const int BK = 16;
    float* As = reinterpret_cast<float*>(sm_raw);
    float* Bs = As + 16 * 132;

    int ty = tid >> 4, tx = tid & 15;
    int aRow = tid >> 2, aCol = (tid & 3) << 2;

    for (int half = 0; half < 2; half++) {
        int n0h = n0 + half * 128;
        float acc[8][8];
        #pragma unroll
        for (int i = 0; i < 8; i++)
            #pragma unroll
            for (int j = 0; j < 8; j++) acc[i][j] = 0.f;

        for (int kt = 0; kt < K; kt += BK) {
            #pragma unroll
            for (int p = 0; p < 2; p++) {
                int r = aRow + p * 64;
                float4 v = *reinterpret_cast<const float4*>(
                    &A[(size_t)(m0 + r) * K + kt + aCol]);
                As[(aCol + 0) * 132 + r] = v.x;
                As[(aCol + 1) * 132 + r] = v.y;
                As[(aCol + 2) * 132 + r] = v.z;
                As[(aCol + 3) * 132 + r] = v.w;
            }
            #pragma unroll
            for (int p = 0; p < 2; p++) {
                int n = aRow + p * 64;
                float4 v = *reinterpret_cast<const float4*>(
                    &Bt[(size_t)(n0h + n) * K + kt + aCol]);
                Bs[(aCol + 0) * 132 + n] = v.x;
                Bs[(aCol + 1) * 132 + n] = v.y;
                Bs[(aCol + 2) * 132 + n] = v.z;
                Bs[(aCol + 3) * 132 + n] = v.w;
            }
            __syncthreads();
            #pragma unroll
            for (int k = 0; k < BK; k++) {
                float a[8], b[8];
                #pragma unroll
                for (int i = 0; i < 8; i++) a[i] = As[k * 132 + ty * 8 + i];
                #pragma unroll
                for (int j = 0; j < 8; j++) b[j] = Bs[k * 132 + tx * 8 + j];
                #pragma unroll
                for (int i = 0; i < 8; i++)
                    #pragma unroll
                    for (int j = 0; j < 8; j++)
                        acc[i][j] += a[i] * b[j];
            }
            __syncthreads();
        }

        #pragma unroll
        for (int i = 0; i < 8; i++) {
            size_t r = m0 + ty * 8 + i;
            #pragma unroll
            for (int j4 = 0; j4 < 2; j4++) {
                int c = n0h + tx * 8 + j4 * 4;
                float4 v;
                v.x = acc[i][j4 * 4 + 0] + bias[c + 0];
                v.y = acc[i][j4 * 4 + 1] + bias[c + 1];
                v.z = acc[i][j4 * 4 + 2] + bias[c + 2];
                v.w = acc[i][j4 * 4 + 3] + bias[c + 3];
                if (ACT == 1) {
                    float4 av = *reinterpret_cast<const float4*>(&add[r * N + c]);
                    v.x = v.x / (1.f + expf(-v.x)) + av.x;
                    v.y = v.y / (1.f + expf(-v.y)) + av.y;
                    v.z = v.z / (1.f + expf(-v.z)) + av.z;
                    v.w = v.w / (1.f + expf(-v.w)) + av.w;
                }
                *reinterpret_cast<float4*>(&C[r * N + c]) = v;
            }
        }
    }
#endif
}

// ---------------- prep kernels -------------------------------------------
__global__ __launch_bounds__(256)
void round_copy_kernel(const float* __restrict__ src, float* __restrict__ dst)
{
    int i = blockIdx.x * 256 + threadIdx.x;
    float4 v = reinterpret_cast<const float4*>(src)[i];
    v.x = roundtf(v.x); v.y = roundtf(v.y);
    v.z = roundtf(v.z); v.w = roundtf(v.w);
    reinterpret_cast<float4*>(dst)[i] = v;
}

__global__ __launch_bounds__(256)
void transpose_round_kernel(const float* __restrict__ src, float* __restrict__ dst,
                            int K, int N)
{
    __shared__ float t[32][33];
    int n0 = blockIdx.x * 32, k0 = blockIdx.y * 32;
    #pragma unroll
    for (int j = 0; j < 4; j++) {
        int k = k0 + threadIdx.y + 8 * j;
        t[threadIdx.y + 8 * j][threadIdx.x] = src[(size_t)k * N + n0 + threadIdx.x];
    }
    __syncthreads();
    #pragma unroll
    for (int j = 0; j < 4; j++) {
        int n = n0 + threadIdx.y + 8 * j;
        dst[(size_t)n * K + k0 + threadIdx.x] =
            roundtf(t[threadIdx.x][threadIdx.y + 8 * j]);
    }
}

// ---------------- RoPE (in-place, outputs rounded to tf32 grid) ----------
__global__ __launch_bounds__(256)
void rope_kernel(float* __restrict__ fused, const float* __restrict__ rope_w)
{
    int idx = blockIdx.x * blockDim.x + threadIdx.x;
    int i = idx & 63;
    int h = (idx >> 6) & 15;
    int s = (idx >> 10) & 2047;
    int b = idx >> 21;

    float* base = fused + (size_t)(b * Sv + s) * N_FUSED + h * DHv;
    float c0, s0, c1, s1;
    sincosf(rope_w[s * DHv + i],      &s0, &c0);
    sincosf(rope_w[s * DHv + i + 64], &s1, &c1);
    const float rs = 0.08838834764831845f;

    float q0 = base[i], q1 = base[i + 64];
    base[i]      = roundtf((q0 * c0 + q1 * s0) * rs);
    base[i + 64] = roundtf((q1 * c1 + q0 * s1) * rs);

    float k0 = base[Dv + i], k1 = base[Dv + i + 64];
    base[Dv + i]      = roundtf(k0 * c0 + k1 * s0);
    base[Dv + i + 64] = roundtf(k1 * c1 + k0 * s1);
}

// ---------------- Flash attention: tcgen05 tf32 (R9-passing) --------------
#define AT_Q    1024
#define AT_K    (AT_Q + 65536)
#define AT_V    (AT_K + 65536)
#define AT_P    (AT_V + 32768)
#define ASMEM_TOTAL (AT_P + 32768)

__global__ __launch_bounds__(128, 1)
void attn_tc(const float* __restrict__ fused)
{
    extern __shared__ char sm_raw[];
    int tid = threadIdx.x;
    int qt = 15 - blockIdx.x;             // big tiles first
    int bh = blockIdx.y;
    int b = bh >> 4, h = bh & 15;
    const float* qbase = fused + (size_t)b * Sv * N_FUSED + h * DHv;
    const float* kbase = qbase + Dv;
    const float* vbase = qbase + 2 * Dv;

#if HAS_TCGEN05
    uint32_t sb = smem_u32(sm_raw);
    int wid = tid >> 5, lid = tid & 31;

    if (wid == 0)
        asm volatile("tcgen05.alloc.cta_group::1.sync.aligned.shared::cta.b32 [%0], %1;"
                     :: "r"(sb), "r"(256u) : "memory");
    if (tid == 0) { mbar_init(sb + 8, 1); mbar_init(sb + 16, 1); }
    __syncthreads();
    uint32_t tmem;
    asm volatile("ld.shared.b32 %0, [%1];" : "=r"(tmem) : "r"(sb));
    if (wid == 0)
        asm volatile("tcgen05.relinquish_alloc_permit.cta_group::1.sync.aligned;");

    uint32_t TS = tmem;          // S: cols 0-63
    uint32_t TO = tmem + 64;     // O: cols 64-191

    for (int u = tid; u < 4096; u += 128) {
        int c = u >> 10;
        int rem = u & 1023;
        int r = rem >> 3, f4 = rem & 7;
        uint32_t off = r * 128 + f4 * 16;
        off ^= (off >> 3) & 0x70;
        cpasync16(sb + AT_Q + c * 16384 + off,
                  qbase + (size_t)(qt * 128 + r) * N_FUSED + c * 32 + f4 * 4);
    }
    auto loadK = [&](int kt, int buf) {
        const float* kb2 = kbase + (size_t)(kt * 64) * N_FUSED;
        for (int u = tid; u < 2048; u += 128) {
            int c = u >> 9;
            int rem = u & 511;
            int r = rem >> 3, f4 = rem & 7;
            uint32_t off = r * 128 + f4 * 16;
            off ^= (off >> 3) & 0x70;
            cpasync16(sb + AT_K + buf * 32768 + c * 8192 + off,
                      kb2 + (size_t)r * N_FUSED + c * 32 + f4 * 4);
        }
        asm volatile("cp.async.commit_group;" ::: "memory");
    };
    loadK(0, 0);

    const int nkv = 2 * qt + 2;
    const uint32_t idescS = (1u << 4) | (2u << 7) | (2u << 10) |
                            (8u << 17) | (8u << 24);
    const uint32_t idescO = (1u << 4) | (2u << 7) | (2u << 10) |
                            (16u << 17) | (8u << 24);

    float m_run = -1e30f, l_run = 0.f;
    uint32_t phS = 0, phPV = 0;
    int qrow = qt * 128 + tid;

    for (int kt = 0; kt < nkv; kt++) {
        int kb = kt & 1;
        asm volatile("cp.async.wait_group 0;" ::: "memory");
        asm volatile("fence.proxy.async.shared::cta;" ::: "memory");
        __syncthreads();

        if (wid == 0 && elect_one()) {
            #pragma unroll
            for (int c = 0; c < 4; c++) {
                uint64_t ad = make_desc_sw128(sb + AT_Q + c * 16384);
                uint64_t bd = make_desc_sw128(sb + AT_K + kb * 32768 + c * 8192);
                #pragma unroll
                for (int kk = 0; kk < 4; kk++)
                    mma_tf32(TS, ad + kk * 2, bd + kk * 2, idescS,
                             (c > 0 || kk > 0) ? 1u : 0u);
            }
            asm volatile(
                "tcgen05.commit.cta_group::1.mbarrier::arrive::one.shared::cluster.b64 [%0];"
                :: "r"(sb + 8) : "memory");
        }

        if (kt + 1 < nkv) loadK(kt + 1, kb ^ 1);

        if (kt > 0) {
            mbar_wait(sb + 16, phPV); phPV ^= 1;
            asm volatile("tcgen05.fence::after_thread_sync;" ::: "memory");
        }

        {
            const float* vb2 = vbase + (size_t)(kt * 64) * N_FUSED;
            #pragma unroll
            for (int ch = 0; ch < 2; ch++) {
                #pragma unroll
                for (int g = 0; g < 2; g++) {
                    int kvq = ch * 32 + g * 16 + wid * 4;
                    #pragma unroll
                    for (int i = 0; i < 4; i++) {
                        int dh = lid + 32 * i;
                        uint32_t v0 = f2tf32(vb2[(size_t)(kvq + 0) * N_FUSED + dh]);
                        uint32_t v1 = f2tf32(vb2[(size_t)(kvq + 1) * N_FUSED + dh]);
                        uint32_t v2 = f2tf32(vb2[(size_t)(kvq + 2) * N_FUSED + dh]);
                        uint32_t v3 = f2tf32(vb2[(size_t)(kvq + 3) * N_FUSED + dh]);
                        uint32_t off = dh * 128 + g * 64 + wid * 16;
                        off ^= (off >> 3) & 0x70;
                        asm volatile("st.shared.v4.b32 [%0], {%1,%2,%3,%4};"
                                     :: "r"(sb + AT_V + ch * 16384 + off),
                                        "r"(v0), "r"(v1), "r"(v2), "r"(v3)
                                     : "memory");
                    }
                }
            }
        }

        mbar_wait(sb + 8, phS); phS ^= 1;
        asm volatile("tcgen05.fence::after_thread_sync;" ::: "memory");

        float sv[64];
        {
            uint32_t rr[32];
            TLD_X32(rr, TS);
            asm volatile("tcgen05.wait::ld.sync.aligned;" ::: "memory");
            int kvb = kt * 64;
            #pragma unroll
            for (int j = 0; j < 32; j++)
                sv[j] = (kvb + j > qrow) ? -1e30f : __uint_as_float(rr[j]);
            TLD_X32(rr, TS + 32);
            asm volatile("tcgen05.wait::ld.sync.aligned;" ::: "memory");
            #pragma unroll
            for (int j = 0; j < 32; j++)
                sv[32 + j] = (kvb + 32 + j > qrow) ? -1e30f : __uint_as_float(rr[j]);
        }
        float mx = m_run;
        #pragma unroll
        for (int j = 0; j < 64; j++) mx = fmaxf(mx, sv[j]);
        float alpha = __expf(m_run - mx);
        float ssum = 0.f;
        #pragma unroll
        for (int j = 0; j < 64; j++) {
            float p = roundtf(__expf(sv[j] - mx));
            sv[j] = p;
            ssum += p;
        }
        l_run = l_run * alpha + ssum;
        m_run = mx;

        #pragma unroll
        for (int ch = 0; ch < 2; ch++) {
            #pragma unroll
            for (int f4 = 0; f4 < 8; f4++) {
                uint32_t off = tid * 128 + f4 * 16;
                off ^= (off >> 3) & 0x70;
                int j = ch * 32 + f4 * 4;
                asm volatile("st.shared.v4.b32 [%0], {%1,%2,%3,%4};"
                             :: "r"(sb + AT_P + ch * 16384 + off),
                                "r"(__float_as_uint(sv[j + 0])),
                                "r"(__float_as_uint(sv[j + 1])),
                                "r"(__float_as_uint(sv[j + 2])),
                                "r"(__float_as_uint(sv[j + 3]))
                             : "memory");
            }
        }

        if (kt > 0) {
            uint32_t allone = __all_sync(0xffffffffu, alpha == 1.0f);
            if (!allone) {
                #pragma unroll 1
                for (int c2 = 0; c2 < 4; c2++) {
                    uint32_t rr[32];
                    TLD_X32(rr, TO + c2 * 32);
                    asm volatile("tcgen05.wait::ld.sync.aligned;" ::: "memory");
                    #pragma unroll
                    for (int j = 0; j < 32; j++)
                        rr[j] = __float_as_uint(__uint_as_float(rr[j]) * alpha);
                    TST_X32(TO + c2 * 32, rr);
                }
                asm volatile("tcgen05.wait::st.sync.aligned;" ::: "memory");
            }
        }
        asm volatile("tcgen05.fence::before_thread_sync;" ::: "memory");
        asm volatile("fence.proxy.async.shared::cta;" ::: "memory");
        __syncthreads();

        if (wid == 0 && elect_one()) {
            asm volatile("tcgen05.fence::after_thread_sync;" ::: "memory");
            #pragma unroll
            for (int ch = 0; ch < 2; ch++) {
                uint64_t ad = make_desc_sw128(sb + AT_P + ch * 16384);
                uint64_t bd = make_desc_sw128(sb + AT_V + ch * 16384);
                #pragma unroll
                for (int kk = 0; kk < 4; kk++)
                    mma_tf32(TO, ad + kk * 2, bd + kk * 2, idescO,
                             (kt > 0 || ch > 0 || kk > 0) ? 1u : 0u);
            }
            asm volatile(
                "tcgen05.commit.cta_group::1.mbarrier::arrive::one.shared::cluster.b64 [%0];"
                :: "r"(sb + 16) : "memory");
        }
    }

    mbar_wait(sb + 16, phPV);
    asm volatile("tcgen05.fence::after_thread_sync;" ::: "memory");

    float inv = 1.f / l_run;
    size_t ob = (size_t)(b * Sv + qt * 128 + tid) * Dv + h * DHv;
    #pragma unroll 1
    for (int c2 = 0; c2 < 4; c2++) {
        uint32_t rr[32];
        TLD_X32(rr, TO + c2 * 32);
        asm volatile("tcgen05.wait::ld.sync.aligned;" ::: "memory");
        #pragma unroll
        for (int j = 0; j < 32; j += 4) {
            float4 v;
            v.x = roundtf(__uint_as_float(rr[j + 0]) * inv);
            v.y = roundtf(__uint_as_float(rr[j + 1]) * inv);
            v.z = roundtf(__uint_as_float(rr[j + 2]) * inv);
            v.w = roundtf(__uint_as_float(rr[j + 3]) * inv);
            *reinterpret_cast<float4*>(&g_o[ob + c2 * 32 + j]) = v;
        }
    }
    __syncthreads();
    if (wid == 0)
        asm volatile("tcgen05.dealloc.cta_group::1.sync.aligned.b32 %0, %1;"
                     :: "r"(tmem), "r"(256u));

#else  // SIMT fallback
    float* Qs = reinterpret_cast<float*>(sm_raw);
    float* Ks = Qs + 128 * 128;
    float* Vs = Ks + 32 * 128;

    for (int u = tid; u < 128 * 32; u += 128) {
        int r = u >> 5, c4 = (u & 31) << 2;
        float4 v = *reinterpret_cast<const float4*>(
            &qbase[(size_t)(qt * 128 + r) * N_FUSED + c4]);
        *reinterpret_cast<float4*>(&Qs[r * 128 + c4]) = v;
    }
    float O[128];
    #pragma unroll
    for (int d = 0; d < 128; d++) O[d] = 0.f;
    float m = -1e30f, l = 0.f;
    int qglob = qt * 128 + tid;
    int nkv = (qt + 1) * 128 / 32;

    for (int kvt = 0; kvt < nkv; kvt++) {
        __syncthreads();
        for (int u = tid; u < 32 * 32; u += 128) {
            int r = u >> 5, c4 = (u & 31) << 2;
            *reinterpret_cast<float4*>(&Ks[r * 128 + c4]) =
                *reinterpret_cast<const float4*>(
                    &kbase[(size_t)(kvt * 32 + r) * N_FUSED + c4]);
            *reinterpret_cast<float4*>(&Vs[r * 128 + c4]) =
                *reinterpret_cast<const float4*>(
                    &vbase[(size_t)(kvt * 32 + r) * N_FUSED + c4]);
        }
        __syncthreads();
        for (int j = 0; j < 32; j++) {
            int kv = kvt * 32 + j;
            float s = -1e30f;
            if (kv <= qglob) {
                s = 0.f;
                for (int k = 0; k < 128; k++)
                    s += Qs[tid * 128 + k] * Ks[j * 128 + k];
            }
            float mn = fmaxf(m, s);
            float a = __expf(m - mn);
            float p = __expf(s - mn);
            l = l * a + p;
            m = mn;
            for (int d = 0; d < 128; d++)
                O[d] = O[d] * a + p * Vs[j * 128 + d];
        }
    }
    float inv = 1.f / l;
    size_t ob = (size_t)(b * Sv + qt * 128 + tid) * Dv + h * DHv;
    for (int d = 0; d < 128; d++)
        g_o[ob + d] = roundtf(O[d] * inv);
#endif
}

// ---------------- block reduction helper ----------------------------------
__device__ __forceinline__ float block_sum256(float v)
{
    __shared__ float red[8];
    int t = threadIdx.x;
    #pragma unroll
    for (int o = 16; o > 0; o >>= 1)
        v += __shfl_xor_sync(0xffffffffu, v, o);
    if ((t & 31) == 0) red[t >> 5] = v;
    __syncthreads();
    float total = 0.f;
    #pragma unroll
    for (int i = 0; i < 8; i++) total += red[i];
    __syncthreads();
    return total;
}

// ---------------- LayerNorm(ff) + ReLU (float4 vectorized) ----------------
__global__ __launch_bounds__(256)
void ln_relu_kernel(const float* __restrict__ fused,
                    const float* __restrict__ gamma,
                    const float* __restrict__ beta,
                    float* __restrict__ out)
{
    int row = blockIdx.x;
    const float4* x4 = reinterpret_cast<const float4*>(
        fused + (size_t)row * N_FUSED + 3 * Dv);
    float4 v[8];
    float s = 0.f;
    #pragma unroll
    for (int i = 0; i < 8; i++) {
        v[i] = x4[threadIdx.x + (i << 8)];
        s += (v[i].x + v[i].y) + (v[i].z + v[i].w);
    }
    float mean = block_sum256(s) * (1.0f / FFv);
    float s2 = 0.f;
    #pragma unroll
    for (int i = 0; i < 8; i++) {
        float dx = v[i].x - mean, dy = v[i].y - mean;
        float dz = v[i].z - mean, dw = v[i].w - mean;
        s2 += (dx * dx + dy * dy) + (dz * dz + dw * dw);
    }
    float var = block_sum256(s2) * (1.0f / FFv);
    float rstd = rsqrtf(var + EPSv);
    float4* o4 = reinterpret_cast<float4*>(out + (size_t)row * FFv);
    const float4* g4 = reinterpret_cast<const float4*>(gamma);
    const float4* b4 = reinterpret_cast<const float4*>(beta);
    #pragma unroll
    for (int i = 0; i < 8; i++) {
        int c = threadIdx.x + (i << 8);
        float4 g = g4[c], bb = b4[c], o;
        o.x = roundtf(fmaxf(g.x * (v[i].x - mean) * rstd + bb.x, 0.f));
        o.y = roundtf(fmaxf(g.y * (v[i].y - mean) * rstd + bb.y, 0.f));
        o.z = roundtf(fmaxf(g.z * (v[i].z - mean) * rstd + bb.z, 0.f));
        o.w = roundtf(fmaxf(g.w * (v[i].w - mean) * rstd + bb.w, 0.f));
        o4[c] = o;
    }
}

// ---------------- final: LayerNorm(sum) (float4 vectorized) ---------------
__global__ __launch_bounds__(256)
void ln_final_kernel(const float* __restrict__ src,
                     const float* __restrict__ gamma,
                     const float* __restrict__ beta,
                     float* __restrict__ out)
{
    int row = blockIdx.x;
    const float4* x4 = reinterpret_cast<const float4*>(src + (size_t)row * Dv);
    float4 v[2];
    float s = 0.f;
    #pragma unroll
    for (int i = 0; i < 2; i++) {
        v[i] = x4[threadIdx.x + (i << 8)];
        s += (v[i].x + v[i].y) + (v[i].z + v[i].w);
    }
    float mean = block_sum256(s) * (1.0f / Dv);
    float s2 = 0.f;
    #pragma unroll
    for (int i = 0; i < 2; i++) {
        float dx = v[i].x - mean, dy = v[i].y - mean;
        float dz = v[i].z - mean, dw = v[i].w - mean;
        s2 += (dx * dx + dy * dy) + (dz * dz + dw * dw);
    }
    float var = block_sum256(s2) * (1.0f / Dv);
    float rstd = rsqrtf(var + EPSv);
    float4* o4 = reinterpret_cast<float4*>(out + (size_t)row * Dv);
    const float4* g4 = reinterpret_cast<const float4*>(gamma);
    const float4* b4 = reinterpret_cast<const float4*>(beta);
    #pragma unroll
    for (int i = 0; i < 2; i++) {
        int c = threadIdx.x + (i << 8);
        float4 g = g4[c], bb = b4[c], o;
        o.x = g.x * (v[i].x - mean) * rstd + bb.x;
        o.y = g.y * (v[i].y - mean) * rstd + bb.y;
        o.z = g.z * (v[i].z - mean) * rstd + bb.z;
        o.w = g.w * (v[i].w - mean) * rstd + bb.w;
        o4[c] = o;
    }
}

// ---------------- launch ---------------------------------------------------
extern "C" void kernel_launch(void* const* d_in, const int* in_sizes, int n_in,
                              void* d_out, int out_size)
{
    const float* x       = (const float*)d_in[0];
    const float* W_fused = (const float*)d_in[1];
    const float* b_fused = (const float*)d_in[2];
    const float* W_attn  = (const float*)d_in[3];
    const float* b_attn  = (const float*)d_in[4];
    const float* W_ff    = (const float*)d_in[5];
    const float* b_ff    = (const float*)d_in[6];
    const float* gamma1  = (const float*)d_in[7];
    const float* beta1   = (const float*)d_in[8];
    const float* gamma2  = (const float*)d_in[9];
    const float* beta2   = (const float*)d_in[10];
    const float* rope_w  = (const float*)d_in[11];
    float* out = (float*)d_out;
    (void)in_sizes; (void)n_in; (void)out_size;

    float *fused, *o, *attn, *h, *ffo, *xr, *wfT, *waT, *ffT;
    cudaGetSymbolAddress((void**)&fused, g_fused);
    cudaGetSymbolAddress((void**)&o,     g_o);
    cudaGetSymbolAddress((void**)&attn,  g_attn);
    cudaGetSymbolAddress((void**)&h,     g_h);
    cudaGetSymbolAddress((void**)&ffo,   g_ffo);
    cudaGetSymbolAddress((void**)&xr,    g_xr);
    cudaGetSymbolAddress((void**)&wfT,   g_wfT);
    cudaGetSymbolAddress((void**)&waT,   g_waT);
    cudaGetSymbolAddress((void**)&ffT,   g_ffT);

    cudaFuncSetAttribute(gemm_tc<0>,
        cudaFuncAttributeMaxDynamicSharedMemorySize, GSMEM_TOTAL);
    cudaFuncSetAttribute(gemm_tc<1>,
        cudaFuncAttributeMaxDynamicSharedMemorySize, GSMEM_TOTAL);
    cudaFuncSetAttribute(attn_tc,
        cudaFuncAttributeMaxDynamicSharedMemorySize, ASMEM_TOTAL);

    // 0. prep
    round_copy_kernel<<<(M_TOT * Dv / 4) / 256, 256>>>(x, xr);
    transpose_round_kernel<<<dim3(N_FUSED / 32, Dv / 32), dim3(32, 8)>>>(
        W_fused, wfT, Dv, N_FUSED);
    transpose_round_kernel<<<dim3(Dv / 32, Dv / 32), dim3(32, 8)>>>(
        W_attn, waT, Dv, Dv);
    transpose_round_kernel<<<dim3(Dv / 32, FFv / 32), dim3(32, 8)>>>(
        W_ff, ffT, FFv, Dv);

    // 1. fused = x @ W_fused + b_fused
    gemm_tc<0><<<dim3(N_FUSED / GBN, M_TOT / GBM), 256, GSMEM_TOTAL>>>(
        xr, wfT, b_fused, nullptr, fused, M_TOT, N_FUSED, Dv);

    // 2. RoPE
    rope_kernel<<<(Bv * Sv * Hv * 64) / 256, 256>>>(fused, rope_w);

    // 3. Flash attention (tcgen05) -> g_o
    attn_tc<<<dim3(16, Bv * Hv), 128, ASMEM_TOTAL>>>(fused);

    // 4. attn = o @ W_attn + b_attn
    gemm_tc<0><<<dim3(Dv / GBN, M_TOT / GBM), 256, GSMEM_TOTAL>>>(
        o, waT, b_attn, nullptr, attn, M_TOT, Dv, Dv);

    // 5. h = relu(LN1(ff))
    ln_relu_kernel<<<M_TOT, 256>>>(fused, gamma1, beta1, h);

    // 6. ffo = silu(h @ W_ff + b_ff) + attn
    gemm_tc<1><<<dim3(Dv / GBN, M_TOT / GBM), 256, GSMEM_TOTAL>>>(
        h, ffT, b_ff, attn, ffo, M_TOT, Dv, FFv);

    // 7. out = LN2(ffo)
    ln_final_kernel<<<M_TOT, 256>>>(ffo, gamma2, beta2, out);
}

// round 15
// speedup vs baseline: 1.5173x; 1.0032x over previous
#include <cuda_runtime.h>
#include <cstdint>
#include <math.h>

#define Bv 2
#define Sv 2048
#define Dv 2048
#define Hv 16
#define DHv 128
#define FFv 8192
#define M_TOT (Bv*Sv)            // 4096
#define N_FUSED (3*Dv + FFv)     // 14336
#define EPSv 1e-6f

#if defined(__CUDA_ARCH__) && (defined(__CUDA_ARCH_FEAT_SM103_ALL) || defined(__CUDA_ARCH_SPECIFIC__))
#define HAS_TCGEN05 1
#else
#define HAS_TCGEN05 0
#endif

// ---------------- scratch (static device globals; no allocations) --------
__device__ float g_fused[58720256];   // 4096 x 14336
__device__ float g_o[8388608];        // 4096 x 2048   (tf32-rounded)
__device__ float g_attn[8388608];     // 4096 x 2048
__device__ float g_h[33554432];       // 4096 x 8192   (tf32-rounded)
__device__ float g_ffo[8388608];      // 4096 x 2048   (attn + silu(ff))
__device__ float g_xr[8388608];       // 4096 x 2048   rounded x
__device__ float g_wfT[29360128];     // 14336 x 2048  W_fused^T rounded
__device__ float g_waT[4194304];      // 2048 x 2048   W_attn^T rounded
__device__ float g_ffT[16777216];     // 2048 x 8192   W_ff^T rounded

// ================= helpers ================================================
__device__ __forceinline__ uint32_t smem_u32(const void* p) {
    uint32_t a;
    asm("{ .reg .u64 t; cvta.to.shared.u64 t, %1; cvt.u32.u64 %0, t; }"
        : "=r"(a) : "l"(p));
    return a;
}
__device__ __forceinline__ uint32_t f2tf32(float x) {
    return (__float_as_uint(x) + 0x1000u) & 0xFFFFE000u;
}
__device__ __forceinline__ float roundtf(float x) {
    return __uint_as_float(f2tf32(x));
}

#if HAS_TCGEN05
__device__ __forceinline__ uint32_t elect_one() {
    uint32_t pred;
    asm volatile("{\n\t.reg .pred p;\n\telect.sync _|p, 0xFFFFFFFF;\n\t"
                 "selp.b32 %0, 1, 0, p;\n\t}" : "=r"(pred));
    return pred;
}
__device__ __forceinline__ void mbar_init(uint32_t a, uint32_t cnt) {
    asm volatile("mbarrier.init.shared.b64 [%0], %1;" :: "r"(a), "r"(cnt) : "memory");
}
__device__ __forceinline__ void mbar_wait(uint32_t a, uint32_t parity) {
    asm volatile(
        "{\n\t.reg .pred P;\n\t"
        "W%=:\n\t"
        "mbarrier.try_wait.parity.acquire.cta.shared::cta.b64 P, [%0], %1, 0x989680;\n\t"
        "@!P bra W%=;\n\t}"
        :: "r"(a), "r"(parity) : "memory");
}
__device__ __forceinline__ uint64_t make_desc_sw128(uint32_t addr) {
    const uint64_t base =
        (uint64_t(2)  << 61) | (uint64_t(1) << 46) |
        (uint64_t(64) << 32) | (uint64_t(1) << 16);
    return base | ((uint64_t)(addr >> 4) & 0x3FFF);
}
__device__ __forceinline__ void mma_tf32(uint32_t d, uint64_t ad, uint64_t bd,
                                         uint32_t idesc, uint32_t en) {
    asm volatile(
        "{\n\t.reg .pred p;\n\t"
        "setp.ne.u32 p, %4, 0;\n\t"
        "tcgen05.mma.cta_group::1.kind::tf32 [%0], %1, %2, %3, {%5, %5, %5, %5}, p;\n\t}"
        :: "r"(d), "l"(ad), "l"(bd), "r"(idesc), "r"(en), "r"(0u) : "memory");
}
__device__ __forceinline__ void cpasync16(uint32_t dst, const void* src) {
    asm volatile("cp.async.cg.shared.global [%0], [%1], 16;"
                 :: "r"(dst), "l"(src) : "memory");
}

#define TLD_X32(r, a)                                                          \
    asm volatile(                                                              \
        "tcgen05.ld.sync.aligned.32x32b.x32.b32 "                              \
        "{%0,%1,%2,%3,%4,%5,%6,%7,%8,%9,%10,%11,%12,%13,%14,%15,"              \
        "%16,%17,%18,%19,%20,%21,%22,%23,%24,%25,%26,%27,%28,%29,%30,%31}, [%32];" \
        : "=r"((r)[0]), "=r"((r)[1]), "=r"((r)[2]), "=r"((r)[3]),              \
          "=r"((r)[4]), "=r"((r)[5]), "=r"((r)[6]), "=r"((r)[7]),              \
          "=r"((r)[8]), "=r"((r)[9]), "=r"((r)[10]), "=r"((r)[11]),            \
          "=r"((r)[12]), "=r"((r)[13]), "=r"((r)[14]), "=r"((r)[15]),          \
          "=r"((r)[16]), "=r"((r)[17]), "=r"((r)[18]), "=r"((r)[19]),          \
          "=r"((r)[20]), "=r"((r)[21]), "=r"((r)[22]), "=r"((r)[23]),          \
          "=r"((r)[24]), "=r"((r)[25]), "=r"((r)[26]), "=r"((r)[27]),          \
          "=r"((r)[28]), "=r"((r)[29]), "=r"((r)[30]), "=r"((r)[31])           \
        : "r"(a))

#define TST_X32(a, r)                                                          \
    asm volatile(                                                              \
        "tcgen05.st.sync.aligned.32x32b.x32.b32 [%0], "                        \
        "{%1,%2,%3,%4,%5,%6,%7,%8,%9,%10,%11,%12,%13,%14,%15,%16,"             \
        "%17,%18,%19,%20,%21,%22,%23,%24,%25,%26,%27,%28,%29,%30,%31,%32};"    \
        :: "r"(a),                                                             \
           "r"((r)[0]), "r"((r)[1]), "r"((r)[2]), "r"((r)[3]),                 \
           "r"((r)[4]), "r"((r)[5]), "r"((r)[6]), "r"((r)[7]),                 \
           "r"((r)[8]), "r"((r)[9]), "r"((r)[10]), "r"((r)[11]),               \
           "r"((r)[12]), "r"((r)[13]), "r"((r)[14]), "r"((r)[15]),             \
           "r"((r)[16]), "r"((r)[17]), "r"((r)[18]), "r"((r)[19]),             \
           "r"((r)[20]), "r"((r)[21]), "r"((r)[22]), "r"((r)[23]),             \
           "r"((r)[24]), "r"((r)[25]), "r"((r)[26]), "r"((r)[27]),             \
           "r"((r)[28]), "r"((r)[29]), "r"((r)[30]), "r"((r)[31])              \
        : "memory")
#endif

// ================= GEMM: C = A(MxK) @ Bt(NxK)^T + bias ===================
// R14-proven config: CTA tile 128x256, BK=32, 2-stage cp.async pipeline,
// tcgen05 MMA, 2 CTAs/SM, 8-warp epilogue. ACT=1: silu then + add[].
#define GBM 128
#define GBN 256
#define GBK 32
#define A_TILE_B (GBM*GBK*4)                 // 16384
#define B_TILE_B (GBN*GBK*4)                 // 32768
#define STAGE_B  (A_TILE_B + B_TILE_B)       // 49152
#define GSMEM_TOTAL (1024 + 2*STAGE_B)       // 99328

template<int ACT>
__global__ __launch_bounds__(256, 2)
void gemm_tc(const float* __restrict__ A, const float* __restrict__ Bt,
             const float* __restrict__ bias, const float* __restrict__ add,
             float* __restrict__ C, int M, int N, int K)
{
    extern __shared__ char sm_raw[];
    int tid = threadIdx.x;
    int m0 = blockIdx.y * GBM, n0 = blockIdx.x * GBN;

#if HAS_TCGEN05
    uint32_t sb = smem_u32(sm_raw);
    int wid = tid >> 5, lid = tid & 31;

    if (wid == 0)
        asm volatile("tcgen05.alloc.cta_group::1.sync.aligned.shared::cta.b32 [%0], %1;"
                     :: "r"(sb), "r"(256u) : "memory");
    if (tid == 0) { mbar_init(sb + 8, 1); mbar_init(sb + 16, 1); }
    __syncthreads();
    uint32_t tmem;
    asm volatile("ld.shared.b32 %0, [%1];" : "=r"(tmem) : "r"(sb));
    if (wid == 0)
        asm volatile("tcgen05.relinquish_alloc_permit.cta_group::1.sync.aligned;");

    const uint32_t idesc = (1u << 4) | (2u << 7) | (2u << 10) |
                           ((GBN / 8) << 17) | ((GBM / 16) << 24);
    const int nk = K / GBK;

    auto load_stage = [&](int it, int s) {
        uint32_t tileA = sb + 1024 + s * STAGE_B;
        uint32_t tileB = tileA + A_TILE_B;
        const float* Ab = A + (size_t)m0 * K + (size_t)it * GBK;
        #pragma unroll
        for (int i = 0; i < 4; i++) {
            int idx = tid + i * 256;
            int m = idx >> 3, f4 = idx & 7;
            uint32_t off = m * 128 + f4 * 16;
            uint32_t sw = off ^ ((off >> 3) & 0x70);
            cpasync16(tileA + sw, Ab + (size_t)m * K + f4 * 4);
        }
        const float* Bb = Bt + (size_t)n0 * K + (size_t)it * GBK;
        #pragma unroll
        for (int i = 0; i < 8; i++) {
            int idx = tid + i * 256;
            int n = idx >> 3, f4 = idx & 7;
            uint32_t off = n * 128 + f4 * 16;
            uint32_t sw = off ^ ((off >> 3) & 0x70);
            cpasync16(tileB + sw, Bb + (size_t)n * K + f4 * 4);
        }
        asm volatile("cp.async.commit_group;" ::: "memory");
    };

    uint32_t ph0 = 0, ph1 = 0;
    load_stage(0, 0);

    for (int it = 0; it < nk; it++) {
        int s = it & 1;
        if (it + 1 < nk) {
            int s2 = (it + 1) & 1;
            if (it >= 1) {
                if (s2 == 0) { mbar_wait(sb + 8,  ph0); ph0 ^= 1; }
                else         { mbar_wait(sb + 16, ph1); ph1 ^= 1; }
            }
            load_stage(it + 1, s2);
            asm volatile("cp.async.wait_group 1;" ::: "memory");
        } else {
            asm volatile("cp.async.wait_group 0;" ::: "memory");
        }
        asm volatile("fence.proxy.async.shared::cta;" ::: "memory");
        __syncthreads();

        if (wid == 0 && elect_one()) {
            uint32_t tileA = sb + 1024 + s * STAGE_B;
            uint64_t ad = make_desc_sw128(tileA);
            uint64_t bd = make_desc_sw128(tileA + A_TILE_B);
            #pragma unroll
            for (int kk = 0; kk < 4; kk++) {
                uint32_t en = (it > 0 || kk > 0) ? 1u : 0u;
                mma_tf32(tmem, ad + kk * 2, bd + kk * 2, idesc, en);
            }
            uint32_t mb = (s == 0) ? sb + 8 : sb + 16;
            asm volatile(
                "tcgen05.commit.cta_group::1.mbarrier::arrive::one.shared::cluster.b64 [%0];"
                :: "r"(mb) : "memory");
        }
    }

    if (((nk - 1) & 1) == 0) mbar_wait(sb + 8,  ph0);
    else                     mbar_wait(sb + 16, ph1);
    asm volatile("tcgen05.fence::after_thread_sync;" ::: "memory");

    // 8-warp epilogue: sub = wid&3 (rows), half = wid>>2 (column half)
    {
        int sub = wid & 3, half = wid >> 2;
        size_t row = (size_t)(m0 + sub * 32 + lid);
        uint32_t tcol = tmem + half * 128;
        int ncol = n0 + half * 128;
        #pragma unroll 1
        for (int c = 0; c < 4; c++) {
            uint32_t r[32];
            TLD_X32(r, tcol + c * 32);
            asm volatile("tcgen05.wait::ld.sync.aligned;" ::: "memory");

            int cb = ncol + c * 32;
            #pragma unroll
            for (int j = 0; j < 32; j += 4) {
                float4 bv = *reinterpret_cast<const float4*>(bias + cb + j);
                float4 o;
                o.x = __uint_as_float(r[j + 0]) + bv.x;
                o.y = __uint_as_float(r[j + 1]) + bv.y;
                o.z = __uint_as_float(r[j + 2]) + bv.z;
                o.w = __uint_as_float(r[j + 3]) + bv.w;
                if (ACT == 1) {
                    float4 av = *reinterpret_cast<const float4*>(
                        add + row * N + cb + j);
                    o.x = o.x / (1.f + expf(-o.x)) + av.x;
                    o.y = o.y / (1.f + expf(-o.y)) + av.y;
                    o.z = o.z / (1.f + expf(-o.z)) + av.z;
                    o.w = o.w / (1.f + expf(-o.w)) + av.w;
                }
                *reinterpret_cast<float4*>(C + row * N + cb + j) = o;
            }
        }
    }
    __syncthreads();
    if (wid == 0)
        asm volatile("tcgen05.dealloc.cta_group::1.sync.aligned.b32 %0, %1;"
                     :: "r"(tmem), "r"(256u));

#else   // ---------------- SIMT fallback (two 128x128 halves) --------------
    const int BK = 16;
    float* As = reinterpret_cast<float*>(sm_raw);
    float* Bs = As + 16 * 132;

    int ty = tid >> 4, tx = tid & 15;
    int aRow = tid >> 2, aCol = (tid & 3) << 2;

    for (int half = 0; half < 2; half++) {
        int n0h = n0 + half * 128;
        float acc[8][8];
        #pragma unroll
        for (int i = 0; i < 8; i++)
            #pragma unroll
            for (int j = 0; j < 8; j++) acc[i][j] = 0.f;

        for (int kt = 0; kt < K; kt += BK) {
            #pragma unroll
            for (int p = 0; p < 2; p++) {
                int r = aRow + p * 64;
                float4 v = *reinterpret_cast<const float4*>(
                    &A[(size_t)(m0 + r) * K + kt + aCol]);
                As[(aCol + 0) * 132 + r] = v.x;
                As[(aCol + 1) * 132 + r] = v.y;
                As[(aCol + 2) * 132 + r] = v.z;
                As[(aCol + 3) * 132 + r] = v.w;
            }
            #pragma unroll
            for (int p = 0; p < 2; p++) {
                int n = aRow + p * 64;
                float4 v = *reinterpret_cast<const float4*>(
                    &Bt[(size_t)(n0h + n) * K + kt + aCol]);
                Bs[(aCol + 0) * 132 + n] = v.x;
                Bs[(aCol + 1) * 132 + n] = v.y;
                Bs[(aCol + 2) * 132 + n] = v.z;
                Bs[(aCol + 3) * 132 + n] = v.w;
            }
            __syncthreads();
            #pragma unroll
            for (int k = 0; k < BK; k++) {
                float a[8], b[8];
                #pragma unroll
                for (int i = 0; i < 8; i++) a[i] = As[k * 132 + ty * 8 + i];
                #pragma unroll
                for (int j = 0; j < 8; j++) b[j] = Bs[k * 132 + tx * 8 + j];
                #pragma unroll
                for (int i = 0; i < 8; i++)
                    #pragma unroll
                    for (int j = 0; j < 8; j++)
                        acc[i][j] += a[i] * b[j];
            }
            __syncthreads();
        }

        #pragma unroll
        for (int i = 0; i < 8; i++) {
            size_t r = m0 + ty * 8 + i;
            #pragma unroll
            for (int j4 = 0; j4 < 2; j4++) {
                int c = n0h + tx * 8 + j4 * 4;
                float4 v;
                v.x = acc[i][j4 * 4 + 0] + bias[c + 0];
                v.y = acc[i][j4 * 4 + 1] + bias[c + 1];
                v.z = acc[i][j4 * 4 + 2] + bias[c + 2];
                v.w = acc[i][j4 * 4 + 3] + bias[c + 3];
                if (ACT == 1) {
                    float4 av = *reinterpret_cast<const float4*>(&add[r * N + c]);
                    v.x = v.x / (1.f + expf(-v.x)) + av.x;
                    v.y = v.y / (1.f + expf(-v.y)) + av.y;
                    v.z = v.z / (1.f + expf(-v.z)) + av.z;
                    v.w = v.w / (1.f + expf(-v.w)) + av.w;
                }
                *reinterpret_cast<float4*>(&C[r * N + c]) = v;
            }
        }
    }
#endif
}

// ---------------- fused prep: round x + transpose+round 3 weights --------
// one launch; segments decoded from blockIdx.x:
//   [0, 8192)              round-copy x -> xr (float4 per thread)
//   [8192, 36864)          W_fused (2048x14336) -> wfT
//   [36864, 40960)         W_attn  (2048x2048)  -> waT
//   [40960, 57344)         W_ff    (8192x2048)  -> ffT
#define PREP_BLOCKS 57344

__global__ __launch_bounds__(256)
void prep_kernel(const float* __restrict__ x,
                 const float* __restrict__ Wf,
                 const float* __restrict__ Wa,
                 const float* __restrict__ Wff,
                 float* __restrict__ xr, float* __restrict__ wfT,
                 float* __restrict__ waT, float* __restrict__ ffT)
{
    int tid = threadIdx.x;
    int b = blockIdx.x;

    if (b < 8192) {                       // ---- round copy x ----
        int i = b * 256 + tid;
        float4 v = reinterpret_cast<const float4*>(x)[i];
        v.x = roundtf(v.x); v.y = roundtf(v.y);
        v.z = roundtf(v.z); v.w = roundtf(v.w);
        reinterpret_cast<float4*>(xr)[i] = v;
        return;
    }
    b -= 8192;

    const float* src; float* dst; int K, N;
    if (b < 28672)        { src = Wf;  dst = wfT; K = Dv;  N = N_FUSED; }
    else if (b < 32768)   { b -= 28672; src = Wa;  dst = waT; K = Dv;  N = Dv; }
    else                  { b -= 32768; src = Wff; dst = ffT; K = FFv; N = Dv; }

    __shared__ float t[32][33];
    int nb = N / 32;
    int bx = b % nb, by = b / nb;
    int tx = tid & 31, ty = tid >> 5;
    int n0 = bx * 32, k0 = by * 32;
    #pragma unroll
    for (int j = 0; j < 4; j++) {
        int k = k0 + ty + 8 * j;
        t[ty + 8 * j][tx] = src[(size_t)k * N + n0 + tx];
    }
    __syncthreads();
    #pragma unroll
    for (int j = 0; j < 4; j++) {
        int n = n0 + ty + 8 * j;
        dst[(size_t)n * K + k0 + tx] = roundtf(t[tx][ty + 8 * j]);
    }
}

// ---------------- RoPE (in-place, outputs rounded to tf32 grid) ----------
__global__ __launch_bounds__(256)
void rope_kernel(float* __restrict__ fused, const float* __restrict__ rope_w)
{
    int idx = blockIdx.x * blockDim.x + threadIdx.x;
    int i = idx & 63;
    int h = (idx >> 6) & 15;
    int s = (idx >> 10) & 2047;
    int b = idx >> 21;

    float* base = fused + (size_t)(b * Sv + s) * N_FUSED + h * DHv;
    float c0, s0, c1, s1;
    sincosf(rope_w[s * DHv + i],      &s0, &c0);
    sincosf(rope_w[s * DHv + i + 64], &s1, &c1);
    const float rs = 0.08838834764831845f;

    float q0 = base[i], q1 = base[i + 64];
    base[i]      = roundtf((q0 * c0 + q1 * s0) * rs);
    base[i + 64] = roundtf((q1 * c1 + q0 * s1) * rs);

    float k0 = base[Dv + i], k1 = base[Dv + i + 64];
    base[Dv + i]      = roundtf(k0 * c0 + k1 * s0);
    base[Dv + i + 64] = roundtf(k1 * c1 + k0 * s1);
}

// ---------------- Flash attention: tcgen05 tf32 (R9-passing) --------------
#define AT_Q    1024
#define AT_K    (AT_Q + 65536)
#define AT_V    (AT_K + 65536)
#define AT_P    (AT_V + 32768)
#define ASMEM_TOTAL (AT_P + 32768)

__global__ __launch_bounds__(128, 1)
void attn_tc(const float* __restrict__ fused)
{
    extern __shared__ char sm_raw[];
    int tid = threadIdx.x;
    int qt = 15 - blockIdx.x;             // big tiles first
    int bh = blockIdx.y;
    int b = bh >> 4, h = bh & 15;
    const float* qbase = fused + (size_t)b * Sv * N_FUSED + h * DHv;
    const float* kbase = qbase + Dv;
    const float* vbase = qbase + 2 * Dv;

#if HAS_TCGEN05
    uint32_t sb = smem_u32(sm_raw);
    int wid = tid >> 5, lid = tid & 31;

    if (wid == 0)
        asm volatile("tcgen05.alloc.cta_group::1.sync.aligned.shared::cta.b32 [%0], %1;"
                     :: "r"(sb), "r"(256u) : "memory");
    if (tid == 0) { mbar_init(sb + 8, 1); mbar_init(sb + 16, 1); }
    __syncthreads();
    uint32_t tmem;
    asm volatile("ld.shared.b32 %0, [%1];" : "=r"(tmem) : "r"(sb));
    if (wid == 0)
        asm volatile("tcgen05.relinquish_alloc_permit.cta_group::1.sync.aligned;");

    uint32_t TS = tmem;          // S: cols 0-63
    uint32_t TO = tmem + 64;     // O: cols 64-191

    for (int u = tid; u < 4096; u += 128) {
        int c = u >> 10;
        int rem = u & 1023;
        int r = rem >> 3, f4 = rem & 7;
        uint32_t off = r * 128 + f4 * 16;
        off ^= (off >> 3) & 0x70;
        cpasync16(sb + AT_Q + c * 16384 + off,
                  qbase + (size_t)(qt * 128 + r) * N_FUSED + c * 32 + f4 * 4);
    }
    auto loadK = [&](int kt, int buf) {
        const float* kb2 = kbase + (size_t)(kt * 64) * N_FUSED;
        for (int u = tid; u < 2048; u += 128) {
            int c = u >> 9;
            int rem = u & 511;
            int r = rem >> 3, f4 = rem & 7;
            uint32_t off = r * 128 + f4 * 16;
            off ^= (off >> 3) & 0x70;
            cpasync16(sb + AT_K + buf * 32768 + c * 8192 + off,
                      kb2 + (size_t)r * N_FUSED + c * 32 + f4 * 4);
        }
        asm volatile("cp.async.commit_group;" ::: "memory");
    };
    loadK(0, 0);

    const int nkv = 2 * qt + 2;
    const uint32_t idescS = (1u << 4) | (2u << 7) | (2u << 10) |
                            (8u << 17) | (8u << 24);
    const uint32_t idescO = (1u << 4) | (2u << 7) | (2u << 10) |
                            (16u << 17) | (8u << 24);

    float m_run = -1e30f, l_run = 0.f;
    uint32_t phS = 0, phPV = 0;
    int qrow = qt * 128 + tid;

    for (int kt = 0; kt < nkv; kt++) {
        int kb = kt & 1;
        asm volatile("cp.async.wait_group 0;" ::: "memory");
        asm volatile("fence.proxy.async.shared::cta;" ::: "memory");
        __syncthreads();

        if (wid == 0 && elect_one()) {
            #pragma unroll
            for (int c = 0; c < 4; c++) {
                uint64_t ad = make_desc_sw128(sb + AT_Q + c * 16384);
                uint64_t bd = make_desc_sw128(sb + AT_K + kb * 32768 + c * 8192);
                #pragma unroll
                for (int kk = 0; kk < 4; kk++)
                    mma_tf32(TS, ad + kk * 2, bd + kk * 2, idescS,
                             (c > 0 || kk > 0) ? 1u : 0u);
            }
            asm volatile(
                "tcgen05.commit.cta_group::1.mbarrier::arrive::one.shared::cluster.b64 [%0];"
                :: "r"(sb + 8) : "memory");
        }

        if (kt + 1 < nkv) loadK(kt + 1, kb ^ 1);

        if (kt > 0) {
            mbar_wait(sb + 16, phPV); phPV ^= 1;
            asm volatile("tcgen05.fence::after_thread_sync;" ::: "memory");
        }

        {
            const float* vb2 = vbase + (size_t)(kt * 64) * N_FUSED;
            #pragma unroll
            for (int ch = 0; ch < 2; ch++) {
                #pragma unroll
                for (int g = 0; g < 2; g++) {
                    int kvq = ch * 32 + g * 16 + wid * 4;
                    #pragma unroll
                    for (int i = 0; i < 4; i++) {
                        int dh = lid + 32 * i;
                        uint32_t v0 = f2tf32(vb2[(size_t)(kvq + 0) * N_FUSED + dh]);
                        uint32_t v1 = f2tf32(vb2[(size_t)(kvq + 1) * N_FUSED + dh]);
                        uint32_t v2 = f2tf32(vb2[(size_t)(kvq + 2) * N_FUSED + dh]);
                        uint32_t v3 = f2tf32(vb2[(size_t)(kvq + 3) * N_FUSED + dh]);
                        uint32_t off = dh * 128 + g * 64 + wid * 16;
                        off ^= (off >> 3) & 0x70;
                        asm volatile("st.shared.v4.b32 [%0], {%1,%2,%3,%4};"
                                     :: "r"(sb + AT_V + ch * 16384 + off),
                                        "r"(v0), "r"(v1), "r"(v2), "r"(v3)
                                     : "memory");
                    }
                }
            }
        }

        mbar_wait(sb + 8, phS); phS ^= 1;
        asm volatile("tcgen05.fence::after_thread_sync;" ::: "memory");

        float sv[64];
        {
            uint32_t rr[32];
            TLD_X32(rr, TS);
            asm volatile("tcgen05.wait::ld.sync.aligned;" ::: "memory");
            int kvb = kt * 64;
            #pragma unroll
            for (int j = 0; j < 32; j++)
                sv[j] = (kvb + j > qrow) ? -1e30f : __uint_as_float(rr[j]);
            TLD_X32(rr, TS + 32);
            asm volatile("tcgen05.wait::ld.sync.aligned;" ::: "memory");
            #pragma unroll
            for (int j = 0; j < 32; j++)
                sv[32 + j] = (kvb + 32 + j > qrow) ? -1e30f : __uint_as_float(rr[j]);
        }
        float mx = m_run;
        #pragma unroll
        for (int j = 0; j < 64; j++) mx = fmaxf(mx, sv[j]);
        float alpha = __expf(m_run - mx);
        float ssum = 0.f;
        #pragma unroll
        for (int j = 0; j < 64; j++) {
            float p = roundtf(__expf(sv[j] - mx));
            sv[j] = p;
            ssum += p;
        }
        l_run = l_run * alpha + ssum;
        m_run = mx;

        #pragma unroll
        for (int ch = 0; ch < 2; ch++) {
            #pragma unroll
            for (int f4 = 0; f4 < 8; f4++) {
                uint32_t off = tid * 128 + f4 * 16;
                off ^= (off >> 3) & 0x70;
                int j = ch * 32 + f4 * 4;
                asm volatile("st.shared.v4.b32 [%0], {%1,%2,%3,%4};"
                             :: "r"(sb + AT_P + ch * 16384 + off),
                                "r"(__float_as_uint(sv[j + 0])),
                                "r"(__float_as_uint(sv[j + 1])),
                                "r"(__float_as_uint(sv[j + 2])),
                                "r"(__float_as_uint(sv[j + 3]))
                             : "memory");
            }
        }

        if (kt > 0) {
            uint32_t allone = __all_sync(0xffffffffu, alpha == 1.0f);
            if (!allone) {
                #pragma unroll 1
                for (int c2 = 0; c2 < 4; c2++) {
                    uint32_t rr[32];
                    TLD_X32(rr, TO + c2 * 32);
                    asm volatile("tcgen05.wait::ld.sync.aligned;" ::: "memory");
                    #pragma unroll
                    for (int j = 0; j < 32; j++)
                        rr[j] = __float_as_uint(__uint_as_float(rr[j]) * alpha);
                    TST_X32(TO + c2 * 32, rr);
                }
                asm volatile("tcgen05.wait::st.sync.aligned;" ::: "memory");
            }
        }
        asm volatile("tcgen05.fence::before_thread_sync;" ::: "memory");
        asm volatile("fence.proxy.async.shared::cta;" ::: "memory");
        __syncthreads();

        if (wid == 0 && elect_one()) {
            asm volatile("tcgen05.fence::after_thread_sync;" ::: "memory");
            #pragma unroll
            for (int ch = 0; ch < 2; ch++) {
                uint64_t ad = make_desc_sw128(sb + AT_P + ch * 16384);
                uint64_t bd = make_desc_sw128(sb + AT_V + ch * 16384);
                #pragma unroll
                for (int kk = 0; kk < 4; kk++)
                    mma_tf32(TO, ad + kk * 2, bd + kk * 2, idescO,
                             (kt > 0 || ch > 0 || kk > 0) ? 1u : 0u);
            }
            asm volatile(
                "tcgen05.commit.cta_group::1.mbarrier::arrive::one.shared::cluster.b64 [%0];"
                :: "r"(sb + 16) : "memory");
        }
    }

    mbar_wait(sb + 16, phPV);
    asm volatile("tcgen05.fence::after_thread_sync;" ::: "memory");

    float inv = 1.f / l_run;
    size_t ob = (size_t)(b * Sv + qt * 128 + tid) * Dv + h * DHv;
    #pragma unroll 1
    for (int c2 = 0; c2 < 4; c2++) {
        uint32_t rr[32];
        TLD_X32(rr, TO + c2 * 32);
        asm volatile("tcgen05.wait::ld.sync.aligned;" ::: "memory");
        #pragma unroll
        for (int j = 0; j < 32; j += 4) {
            float4 v;
            v.x = roundtf(__uint_as_float(rr[j + 0]) * inv);
            v.y = roundtf(__uint_as_float(rr[j + 1]) * inv);
            v.z = roundtf(__uint_as_float(rr[j + 2]) * inv);
            v.w = roundtf(__uint_as_float(rr[j + 3]) * inv);
            *reinterpret_cast<float4*>(&g_o[ob + c2 * 32 + j]) = v;
        }
    }
    __syncthreads();
    if (wid == 0)
        asm volatile("tcgen05.dealloc.cta_group::1.sync.aligned.b32 %0, %1;"
                     :: "r"(tmem), "r"(256u));

#else  // SIMT fallback
    float* Qs = reinterpret_cast<float*>(sm_raw);
    float* Ks = Qs + 128 * 128;
    float* Vs = Ks + 32 * 128;

    for (int u = tid; u < 128 * 32; u += 128) {
        int r = u >> 5, c4 = (u & 31) << 2;
        float4 v = *reinterpret_cast<const float4*>(
            &qbase[(size_t)(qt * 128 + r) * N_FUSED + c4]);
        *reinterpret_cast<float4*>(&Qs[r * 128 + c4]) = v;
    }
    float O[128];
    #pragma unroll
    for (int d = 0; d < 128; d++) O[d] = 0.f;
    float m = -1e30f, l = 0.f;
    int qglob = qt * 128 + tid;
    int nkv = (qt + 1) * 128 / 32;

    for (int kvt = 0; kvt < nkv; kvt++) {
        __syncthreads();
        for (int u = tid; u < 32 * 32; u += 128) {
            int r = u >> 5, c4 = (u & 31) << 2;
            *reinterpret_cast<float4*>(&Ks[r * 128 + c4]) =
                *reinterpret_cast<const float4*>(
                    &kbase[(size_t)(kvt * 32 + r) * N_FUSED + c4]);
            *reinterpret_cast<float4*>(&Vs[r * 128 + c4]) =
                *reinterpret_cast<const float4*>(
                    &vbase[(size_t)(kvt * 32 + r) * N_FUSED + c4]);
        }
        __syncthreads();
        for (int j = 0; j < 32; j++) {
            int kv = kvt * 32 + j;
            float s = -1e30f;
            if (kv <= qglob) {
                s = 0.f;
                for (int k = 0; k < 128; k++)
                    s += Qs[tid * 128 + k] * Ks[j * 128 + k];
            }
            float mn = fmaxf(m, s);
            float a = __expf(m - mn);
            float p = __expf(s - mn);
            l = l * a + p;
            m = mn;
            for (int d = 0; d < 128; d++)
                O[d] = O[d] * a + p * Vs[j * 128 + d];
        }
    }
    float inv = 1.f / l;
    size_t ob = (size_t)(b * Sv + qt * 128 + tid) * Dv + h * DHv;
    for (int d = 0; d < 128; d++)
        g_o[ob + d] = roundtf(O[d] * inv);
#endif
}

// ---------------- block reduction helper ----------------------------------
__device__ __forceinline__ float block_sum256(float v)
{
    __shared__ float red[8];
    int t = threadIdx.x;
    #pragma unroll
    for (int o = 16; o > 0; o >>= 1)
        v += __shfl_xor_sync(0xffffffffu, v, o);
    if ((t & 31) == 0) red[t >> 5] = v;
    __syncthreads();
    float total = 0.f;
    #pragma unroll
    for (int i = 0; i < 8; i++) total += red[i];
    __syncthreads();
    return total;
}

// ---------------- LayerNorm(ff) + ReLU (float4 vectorized) ----------------
__global__ __launch_bounds__(256)
void ln_relu_kernel(const float* __restrict__ fused,
                    const float* __restrict__ gamma,
                    const float* __restrict__ beta,
                    float* __restrict__ out)
{
    int row = blockIdx.x;
    const float4* x4 = reinterpret_cast<const float4*>(
        fused + (size_t)row * N_FUSED + 3 * Dv);
    float4 v[8];
    float s = 0.f;
    #pragma unroll
    for (int i = 0; i < 8; i++) {
        v[i] = x4[threadIdx.x + (i << 8)];
        s += (v[i].x + v[i].y) + (v[i].z + v[i].w);
    }
    float mean = block_sum256(s) * (1.0f / FFv);
    float s2 = 0.f;
    #pragma unroll
    for (int i = 0; i < 8; i++) {
        float dx = v[i].x - mean, dy = v[i].y - mean;
        float dz = v[i].z - mean, dw = v[i].w - mean;
        s2 += (dx * dx + dy * dy) + (dz * dz + dw * dw);
    }
    float var = block_sum256(s2) * (1.0f / FFv);
    float rstd = rsqrtf(var + EPSv);
    float4* o4 = reinterpret_cast<float4*>(out + (size_t)row * FFv);
    const float4* g4 = reinterpret_cast<const float4*>(gamma);
    const float4* b4 = reinterpret_cast<const float4*>(beta);
    #pragma unroll
    for (int i = 0; i < 8; i++) {
        int c = threadIdx.x + (i << 8);
        float4 g = g4[c], bb = b4[c], o;
        o.x = roundtf(fmaxf(g.x * (v[i].x - mean) * rstd + bb.x, 0.f));
        o.y = roundtf(fmaxf(g.y * (v[i].y - mean) * rstd + bb.y, 0.f));
        o.z = roundtf(fmaxf(g.z * (v[i].z - mean) * rstd + bb.z, 0.f));
        o.w = roundtf(fmaxf(g.w * (v[i].w - mean) * rstd + bb.w, 0.f));
        o4[c] = o;
    }
}

// ---------------- final: LayerNorm(sum) (float4 vectorized) ---------------
__global__ __launch_bounds__(256)
void ln_final_kernel(const float* __restrict__ src,
                     const float* __restrict__ gamma,
                     const float* __restrict__ beta,
                     float* __restrict__ out)
{
    int row = blockIdx.x;
    const float4* x4 = reinterpret_cast<const float4*>(src + (size_t)row * Dv);
    float4 v[2];
    float s = 0.f;
    #pragma unroll
    for (int i = 0; i < 2; i++) {
        v[i] = x4[threadIdx.x + (i << 8)];
        s += (v[i].x + v[i].y) + (v[i].z + v[i].w);
    }
    float mean = block_sum256(s) * (1.0f / Dv);
    float s2 = 0.f;
    #pragma unroll
    for (int i = 0; i < 2; i++) {
        float dx = v[i].x - mean, dy = v[i].y - mean;
        float dz = v[i].z - mean, dw = v[i].w - mean;
        s2 += (dx * dx + dy * dy) + (dz * dz + dw * dw);
    }
    float var = block_sum256(s2) * (1.0f / Dv);
    float rstd = rsqrtf(var + EPSv);
    float4* o4 = reinterpret_cast<float4*>(out + (size_t)row * Dv);
    const float4* g4 = reinterpret_cast<const float4*>(gamma);
    const float4* b4 = reinterpret_cast<const float4*>(beta);
    #pragma unroll
    for (int i = 0; i < 2; i++) {
        int c = threadIdx.x + (i << 8);
        float4 g = g4[c], bb = b4[c], o;
        o.x = g.x * (v[i].x - mean) * rstd + bb.x;
        o.y = g.y * (v[i].y - mean) * rstd + bb.y;
        o.z = g.z * (v[i].z - mean) * rstd + bb.z;
        o.w = g.w * (v[i].w - mean) * rstd + bb.w;
        o4[c] = o;
    }
}

// ---------------- launch ---------------------------------------------------
extern "C" void kernel_launch(void* const* d_in, const int* in_sizes, int n_in,
                              void* d_out, int out_size)
{
    const float* x       = (const float*)d_in[0];
    const float* W_fused = (const float*)d_in[1];
    const float* b_fused = (const float*)d_in[2];
    const float* W_attn  = (const float*)d_in[3];
    const float* b_attn  = (const float*)d_in[4];
    const float* W_ff    = (const float*)d_in[5];
    const float* b_ff    = (const float*)d_in[6];
    const float* gamma1  = (const float*)d_in[7];
    const float* beta1   = (const float*)d_in[8];
    const float* gamma2  = (const float*)d_in[9];
    const float* beta2   = (const float*)d_in[10];
    const float* rope_w  = (const float*)d_in[11];
    float* out = (float*)d_out;
    (void)in_sizes; (void)n_in; (void)out_size;

    float *fused, *o, *attn, *h, *ffo, *xr, *wfT, *waT, *ffT;
    cudaGetSymbolAddress((void**)&fused, g_fused);
    cudaGetSymbolAddress((void**)&o,     g_o);
    cudaGetSymbolAddress((void**)&attn,  g_attn);
    cudaGetSymbolAddress((void**)&h,     g_h);
    cudaGetSymbolAddress((void**)&ffo,   g_ffo);
    cudaGetSymbolAddress((void**)&xr,    g_xr);
    cudaGetSymbolAddress((void**)&wfT,   g_wfT);
    cudaGetSymbolAddress((void**)&waT,   g_waT);
    cudaGetSymbolAddress((void**)&ffT,   g_ffT);

    cudaFuncSetAttribute(gemm_tc<0>,
        cudaFuncAttributeMaxDynamicSharedMemorySize, GSMEM_TOTAL);
    cudaFuncSetAttribute(gemm_tc<1>,
        cudaFuncAttributeMaxDynamicSharedMemorySize, GSMEM_TOTAL);
    cudaFuncSetAttribute(attn_tc,
        cudaFuncAttributeMaxDynamicSharedMemorySize, ASMEM_TOTAL);

    // 0. prep (single fused launch: round x + transpose+round 3 weights)
    prep_kernel<<<PREP_BLOCKS, 256>>>(x, W_fused, W_attn, W_ff,
                                      xr, wfT, waT, ffT);

    // 1. fused = x @ W_fused + b_fused
    gemm_tc<0><<<dim3(N_FUSED / GBN, M_TOT / GBM), 256, GSMEM_TOTAL>>>(
        xr, wfT, b_fused, nullptr, fused, M_TOT, N_FUSED, Dv);

    // 2. RoPE
    rope_kernel<<<(Bv * Sv * Hv * 64) / 256, 256>>>(fused, rope_w);

    // 3. Flash attention (tcgen05) -> g_o
    attn_tc<<<dim3(16, Bv * Hv), 128, ASMEM_TOTAL>>>(fused);

    // 4. attn = o @ W_attn + b_attn
    gemm_tc<0><<<dim3(Dv / GBN, M_TOT / GBM), 256, GSMEM_TOTAL>>>(
        o, waT, b_attn, nullptr, attn, M_TOT, Dv, Dv);

    // 5. h = relu(LN1(ff))
    ln_relu_kernel<<<M_TOT, 256>>>(fused, gamma1, beta1, h);

    // 6. ffo = silu(h @ W_ff + b_ff) + attn
    gemm_tc<1><<<dim3(Dv / GBN, M_TOT / GBM), 256, GSMEM_TOTAL>>>(
        h, ffT, b_ff, attn, ffo, M_TOT, Dv, FFv);

    // 7. out = LN2(ffo)
    ln_final_kernel<<<M_TOT, 256>>>(ffo, gamma2, beta2, out);
}